// round 13
// baseline (speedup 1.0000x reference)
#include <cuda_runtime.h>
#include <cuda_fp16.h>
#include <math.h>
#include <stdint.h>
#include <string.h>

#define BSZ   8192
#define DD    512
#define UNITS 256
#define NRIM  6
#define TOPK  4
#define NIH   2
#define IKS   64
#define IVS   400
#define NCH   4
#define CKS   32
#define CVS   100

#define BF (BSZ*NRIM*UNITS)
#define GSM_PIPE  56832   // 3 stages * (128*20 + 16*136) u32 * 4B
#define GSM_STAGE 67584   // 128*132 floats (LSTM epilogue staging; >= GSM_PIPE)

// ---------------- scratch ------------------------------------------------------
__device__ float g_kx  [BSZ*128];
__device__ float g_vx  [BSZ*800];
__device__ float g_q   [BSZ*NRIM*128];
__device__ float g_mask[BSZ*NRIM];
__device__ float g_hnew[BF];
__device__ float g_ckqv[BSZ*NRIM*768];       // [k 0:128 | q 128:256 | v 256:656 | pad]
// half A-side operands (u32 = half2 k-pairs, K padded to mult-of-32 halves)
__device__ uint32_t g_xh   [BSZ*256];
__device__ uint32_t g_hsh  [BSZ*768];
__device__ uint32_t g_rnnh [BSZ*NRIM*208];
__device__ __half   g_hnewh[BF];
__device__ __half   g_ctxh [BSZ*NRIM*416];
// packed half2 weights, layout [k/2][Npad], zero-padded
__device__ uint32_t g_wh_val[256*896];
__device__ uint32_t g_wh_pre[6*336*1024];    // gate-interleaved cols: n' = u*4+gate
__device__ uint32_t g_wh_kqv[6*128*768];
__device__ uint32_t g_wh_o  [6*208*256];

// ---------------- fp32 -> half2 convert ---------------------------------------
__global__ void f2h(const float2* __restrict__ src, uint32_t* __restrict__ dst, int n)
{
    const int i = blockIdx.x * 256 + threadIdx.x;
    if (i >= n) return;
    float2 v = src[i];
    __half2 h = __floats2half2_rn(v.x, v.y);
    uint32_t u; memcpy(&u, &h, 4);
    dst[i] = u;
}

// ---------------- weight pack: Wh[k2][n] = half2(W(2k2,n), W(2k2+1,n)) --------
__global__ void pack_w(const float* __restrict__ W1, int K1, int ldw1, long sW1,
                       const float* __restrict__ W2, int K2, int ldw2, long sW2,
                       uint32_t* __restrict__ Wh, int N, int Npad, int Ktot, long sWh)
{
    const int z = blockIdx.z;
    const long idx = (long)blockIdx.x * 256 + threadIdx.x;
    const int rows = Ktot / 2;
    if (idx >= (long)rows * Npad) return;
    const int k2 = (int)(idx / Npad);
    const int n  = (int)(idx % Npad);
    const int K1p = (K1 + 31) & ~31;

    float v[2];
#pragma unroll
    for (int e = 0; e < 2; e++) {
        const int k = 2 * k2 + e;
        float x = 0.f;
        if (n < N) {
            if (k < K1p) { if (k < K1) x = W1[(long)z * sW1 + (long)k * ldw1 + n]; }
            else { const int ks = k - K1p; if (ks < K2) x = W2[(long)z * sW2 + (long)ks * ldw2 + n]; }
        }
        v[e] = x;
    }
    __half2 h = __float22half2_rn(make_float2(v[0], v[1]));
    uint32_t u; memcpy(&u, &h, 4);
    Wh[(long)z * sWh + idx] = u;
}

// ---------------- preact weight pack: gate-interleaved cols --------------------
// out col n' (0..1023): unit u = n'>>2, gate g = n'&3  ->  orig col n = g*256+u
// rows k2 (0..335): halves kg = 2k2+e; kg<416 -> i2h row kg (0 if >=400); else h2h row kg-416
__global__ void pack_pre(const float* __restrict__ i2h, const float* __restrict__ h2h,
                         uint32_t* __restrict__ Wh)
{
    const int z = blockIdx.z;
    const int idx = blockIdx.x * 256 + threadIdx.x;    // 0..344063
    const int k2 = idx >> 10, np = idx & 1023;
    const int u = np >> 2, gte = np & 3;
    const int n = gte * 256 + u;
    float v[2];
#pragma unroll
    for (int e = 0; e < 2; e++) {
        const int k = 2 * k2 + e;
        float x = 0.f;
        if (k < 416) { if (k < 400) x = i2h[((long)z * 400 + k) * 1024 + n]; }
        else         { x = h2h[((long)z * 256 + (k - 416)) * 1024 + n]; }
        v[e] = x;
    }
    __half2 h = __float22half2_rn(make_float2(v[0], v[1]));
    uint32_t u32v; memcpy(&u32v, &h, 4);
    Wh[(long)z * (336L * 1024) + idx] = u32v;
}

// ---------------- merged comm weight pack: [k2=128][768] per rim ---------------
__global__ void pack_kqv(const float* __restrict__ Wk, const float* __restrict__ Wq,
                         const float* __restrict__ Wv, uint32_t* __restrict__ Wh)
{
    const int z = blockIdx.z;
    const int idx = blockIdx.x * 256 + threadIdx.x;   // 0..98303
    const int k2 = idx / 768, n = idx % 768;
    float v[2];
#pragma unroll
    for (int e = 0; e < 2; e++) {
        const int k = 2 * k2 + e;
        float x = 0.f;
        if (n < 128)      x = Wk[((long)z * 256 + k) * 128 + n];
        else if (n < 256) x = Wq[((long)z * 256 + k) * 128 + (n - 128)];
        else if (n < 656) x = Wv[((long)z * 256 + k) * 400 + (n - 256)];
        v[e] = x;
    }
    __half2 h = __float22half2_rn(make_float2(v[0], v[1]));
    uint32_t u; memcpy(&u, &h, 4);
    Wh[(long)z * (128L * 768) + idx] = u;
}

// =================== fp16 tensor-core GEMM: cp.async 3-stage pipeline =========
// ep=0: C = A@W (+bias).  ep=1: LSTM epilogue (gate-interleaved W).  ep=2: final-h epilogue.
__device__ __forceinline__ void mma_fp16(float* d, const uint32_t* a, const uint32_t* b) {
    asm volatile(
        "mma.sync.aligned.m16n8k16.row.col.f32.f16.f16.f32 "
        "{%0,%1,%2,%3}, {%4,%5,%6,%7}, {%8,%9}, {%0,%1,%2,%3};\n"
        : "+f"(d[0]), "+f"(d[1]), "+f"(d[2]), "+f"(d[3])
        : "r"(a[0]), "r"(a[1]), "r"(a[2]), "r"(a[3]),
          "r"(b[0]), "r"(b[1]));
}
__device__ __forceinline__ void cpa16(uint32_t dst, const void* src) {
    asm volatile("cp.async.ca.shared.global [%0], [%1], 16;\n" :: "r"(dst), "l"(src));
}
#define CP_COMMIT() asm volatile("cp.async.commit_group;\n" ::: "memory")
#define CP_WAIT1()  asm volatile("cp.async.wait_group 1;\n" ::: "memory")
#define CP_WAIT0()  asm volatile("cp.async.wait_group 0;\n" ::: "memory")

__device__ __forceinline__ float sigf(float x) { return 1.f / (1.f + expf(-x)); }

// stage layout (u32): A [128][20] at +0, W [16][136] at +2560; stage stride 4736
__global__ void __launch_bounds__(256) gemm_fp16h(
    const uint32_t* __restrict__ A1, int K1u, int lda1, long sA1,   // u32 units
    const uint32_t* __restrict__ A2, int lda2, long sA2,
    const uint32_t* __restrict__ Wh, int ldwh, long sWh, int Ktotu, // u32 units
    const float* __restrict__ bias, float* __restrict__ C, int N, int ldc, long sC,
    int ep,
    const float* __restrict__ cs, float* __restrict__ outp,
    const float* __restrict__ mask, float* __restrict__ hnew,
    __half* __restrict__ hnewh, const float* __restrict__ hs)
{
    extern __shared__ uint32_t sm[];

    const int tid = threadIdx.x, wid = tid >> 5, lane = tid & 31;
    const int warp_m = (wid & 1) * 64, warp_n = (wid >> 1) * 32;
    const int g = lane >> 2, qd = lane & 3;
    const int m0 = blockIdx.y * 128, n0 = blockIdx.x * 128, z = blockIdx.z;
    A1 += (long)z * sA1;
    A2 += (long)z * sA2;
    Wh += (long)z * sWh;
    if (C) C += (long)z * sC;

    const uint32_t smb = (uint32_t)__cvta_generic_to_shared(sm);
    const int aRow = tid >> 1, aC0 = tid & 1;

    auto issue = [&](int t) {
        const int buf = t % 3;
        const uint32_t sA = smb + (uint32_t)buf * 4736u * 4u;
        const uint32_t sW = sA + 2560u * 4u;
        const int ku0 = t * 16;
#pragma unroll
        for (int c = 0; c < 2; c++) {
            const int o = ku0 + (aC0 + 2 * c) * 4;
            const uint32_t* src = (o < K1u) ? A1 + (long)(m0 + aRow) * lda1 + o
                                            : A2 + (long)(m0 + aRow) * lda2 + (o - K1u);
            cpa16(sA + (uint32_t)(aRow * 20 + (aC0 + 2 * c) * 4) * 4u, src);
        }
#pragma unroll
        for (int i = 0; i < 2; i++) {
            const int idx = i * 256 + tid;
            const int r = idx >> 5, cu = (idx & 31) * 4;
            cpa16(sW + (uint32_t)(r * 136 + cu) * 4u,
                  Wh + (long)(ku0 + r) * ldwh + n0 + cu);
        }
    };

    float acc[4][4][4];
#pragma unroll
    for (int i = 0; i < 4; i++)
#pragma unroll
        for (int j = 0; j < 4; j++)
#pragma unroll
            for (int r = 0; r < 4; r++) acc[i][j][r] = 0.f;

    const int T = Ktotu / 16;   // all call sites have T >= 8
    issue(0); CP_COMMIT();
    issue(1); CP_COMMIT();

    for (int t = 0; t < T; t++) {
        CP_WAIT1();
        __syncthreads();
        if (t + 2 < T) issue(t + 2);
        CP_COMMIT();

        const uint32_t* Asb = sm + (t % 3) * 4736;
        const uint32_t* Wsb = Asb + 2560;
#pragma unroll
        for (int ks2 = 0; ks2 < 2; ks2++) {
            const int kb = ks2 * 8;
            uint32_t af[4][4], bf[4][2];
#pragma unroll
            for (int i = 0; i < 4; i++) {
                const int mb = warp_m + i * 16 + g;
                af[i][0] = Asb[mb * 20 + kb + qd];
                af[i][1] = Asb[(mb + 8) * 20 + kb + qd];
                af[i][2] = Asb[mb * 20 + kb + qd + 4];
                af[i][3] = Asb[(mb + 8) * 20 + kb + qd + 4];
            }
#pragma unroll
            for (int j = 0; j < 4; j++) {
                const int nb = warp_n + j * 8 + g;
                bf[j][0] = Wsb[(kb + qd) * 136 + nb];
                bf[j][1] = Wsb[(kb + qd + 4) * 136 + nb];
            }
#pragma unroll
            for (int i = 0; i < 4; i++)
#pragma unroll
                for (int j = 0; j < 4; j++)
                    mma_fp16(acc[i][j], af[i], bf[j]);
        }
    }

    if (ep == 0) {
        // ---- plain epilogue ----
#pragma unroll
        for (int i = 0; i < 4; i++) {
            const long mA = m0 + warp_m + i * 16 + g;
            const long mB = mA + 8;
#pragma unroll
            for (int j = 0; j < 4; j++) {
                const int n = n0 + warp_n + j * 8 + qd * 2;
#pragma unroll
                for (int e = 0; e < 2; e++) {
                    const int col = n + e;
                    if (col < N) {
                        float vA = acc[i][j][e];
                        float vB = acc[i][j][2 + e];
                        if (bias) { vA += bias[col]; vB += bias[col]; }
                        C[mA * ldc + col] = vA;
                        C[mB * ldc + col] = vB;
                    }
                }
            }
        }
    } else if (ep == 1) {
        // ---- LSTM epilogue: cols are u*4+gate within tile; stage via smem ----
        CP_WAIT0();
        __syncthreads();                // all warps done with pipeline smem
        float* stg = (float*)sm;        // [128][132]
#pragma unroll
        for (int i = 0; i < 4; i++) {
            const int rA = warp_m + i * 16 + g, rB = rA + 8;
#pragma unroll
            for (int j = 0; j < 4; j++) {
                const int cl = warp_n + j * 8 + qd * 2;
                stg[rA * 132 + cl]     = acc[i][j][0];
                stg[rA * 132 + cl + 1] = acc[i][j][1];
                stg[rB * 132 + cl]     = acc[i][j][2];
                stg[rB * 132 + cl + 1] = acc[i][j][3];
            }
        }
        __syncthreads();
        for (int s = tid; s < 128 * 32; s += 256) {
            const int row = s >> 5, uu = s & 31;
            float4 gt = *(const float4*)&stg[row * 132 + uu * 4];
            const long bn = (long)(m0 + row) * NRIM + z;
            const long i  = bn * 256 + (n0 >> 2) + uu;
            const float nc = tanhf(gt.x);
            const float ig = sigf(gt.y);
            const float fg = sigf(gt.z);
            const float og = sigf(gt.w);
            const float cold = cs[i];
            const float c = cold * fg + ig * nc;
            const float h = og * tanhf(c);
            hnew[i]  = h;
            hnewh[i] = __float2half(h);
            outp[2L * BF + i] = (mask[bn] != 0.f) ? c : cold;
        }
    } else {
        // ---- final-h epilogue: h = mask ? acc+hnew : hs ; out[i], out[BF+i] ----
#pragma unroll
        for (int i = 0; i < 4; i++) {
            const long mA = m0 + warp_m + i * 16 + g;
            const long mB = mA + 8;
            const long bnA = mA * NRIM + z, bnB = mB * NRIM + z;
            const float mkA = mask[bnA], mkB = mask[bnB];
#pragma unroll
            for (int j = 0; j < 4; j++) {
                const int col = n0 + warp_n + j * 8 + qd * 2;
#pragma unroll
                for (int e = 0; e < 2; e++) {
                    const long iA = bnA * 256 + col + e;
                    const long iB = bnB * 256 + col + e;
                    const float hA = (mkA != 0.f) ? (acc[i][j][e] + hnew[iA]) : hs[iA];
                    const float hB = (mkB != 0.f) ? (acc[i][j][2 + e] + hnew[iB]) : hs[iB];
                    outp[iA] = hA; outp[BF + iA] = hA;
                    outp[iB] = hB; outp[BF + iB] = hB;
                }
            }
        }
    }
}

// =================== fp32 GEMM (top-k-sensitive path only) ====================
__global__ void __launch_bounds__(256) gemm128(
    const float* __restrict__ A, const float* __restrict__ W,
    const float* __restrict__ bias, float* __restrict__ C,
    int N, int Kd, int lda, int ldw, int ldc,
    long sA, long sW, long sC, int accum)
{
    A += (long)blockIdx.z * sA;
    W += (long)blockIdx.z * sW;
    C += (long)blockIdx.z * sC;

    __shared__ float As[8][128];
    __shared__ float Ws[8][128];

    const int tid = threadIdx.x;
    const int m0  = blockIdx.y * 128;
    const int n0  = blockIdx.x * 128;

    const int aRow = tid >> 1;
    const int aK   = (tid & 1) * 4;
    const int wK   = tid >> 5;
    const int wC   = (tid & 31) * 4;
    const int ty   = tid >> 4;
    const int tx   = tid & 15;

    float acc[8][8];
#pragma unroll
    for (int i = 0; i < 8; i++)
#pragma unroll
        for (int j = 0; j < 8; j++) acc[i][j] = 0.f;

    const float* Aptr = A + (long)(m0 + aRow) * lda + aK;

    for (int k0 = 0; k0 < Kd; k0 += 8) {
        float4 av = *(const float4*)(Aptr + k0);
        As[aK + 0][aRow] = av.x;
        As[aK + 1][aRow] = av.y;
        As[aK + 2][aRow] = av.z;
        As[aK + 3][aRow] = av.w;
        {
            const int col = n0 + wC;
            const float* wp = W + (long)(k0 + wK) * ldw;
            if (col + 3 < N) {
                *(float4*)&Ws[wK][wC] = *(const float4*)(wp + col);
            } else {
#pragma unroll
                for (int j = 0; j < 4; j++)
                    Ws[wK][wC + j] = (col + j < N) ? wp[col + j] : 0.f;
            }
        }
        __syncthreads();

#pragma unroll
        for (int kk = 0; kk < 8; kk++) {
            float a[8], bq[8];
            *(float4*)(a)      = *(const float4*)&As[kk][ty * 8];
            *(float4*)(a + 4)  = *(const float4*)&As[kk][ty * 8 + 4];
            *(float4*)(bq)     = *(const float4*)&Ws[kk][tx * 8];
            *(float4*)(bq + 4) = *(const float4*)&Ws[kk][tx * 8 + 4];
#pragma unroll
            for (int i = 0; i < 8; i++)
#pragma unroll
                for (int j = 0; j < 8; j++)
                    acc[i][j] += a[i] * bq[j];
        }
        __syncthreads();
    }

#pragma unroll
    for (int i = 0; i < 8; i++) {
        const long row = m0 + ty * 8 + i;
#pragma unroll
        for (int j = 0; j < 8; j++) {
            const int col = n0 + tx * 8 + j;
            if (col < N) {
                float v = acc[i][j];
                if (bias)  v += bias[col];
                if (accum) v += C[row * ldc + col];
                C[row * ldc + col] = v;
            }
        }
    }
}

// ---------------- input attention + top-k mask + rnn_in (half out) -------------
__global__ void __launch_bounds__(128) attn_kernel(const float* __restrict__ kb,
                                                   const float* __restrict__ vb)
{
    const int b = blockIdx.x;
    const int t = threadIdx.x;
    __shared__ float sq[NRIM * 128], skx[128], skb[128];
    __shared__ float s2[12], sm[NRIM], sp0[NRIM], sp1[NRIM];

    for (int i = t; i < NRIM * 128; i += 128) sq[i] = g_q[b * NRIM * 128 + i];
    if (t < 128) { skx[t] = g_kx[b * 128 + t]; skb[t] = kb[t]; }
    __syncthreads();

    const int w = t >> 5, lane = t & 31;
    for (int d = w; d < 12; d += 4) {
        const int n = d >> 1, m = d & 1;
        const float* kv = m ? skb : skx;
        float s = 0.f;
        for (int k = lane; k < 128; k += 32) s += sq[n * 128 + k] * kv[k];
#pragma unroll
        for (int o = 16; o; o >>= 1) s += __shfl_xor_sync(0xffffffffu, s, o);
        if (!lane) s2[d] = s * (1.0f / 16.0f);
    }
    __syncthreads();

    if (t < NRIM) {
        const int n = t;
        const float sn = s2[n * 2];
        int rank = 0;
        for (int m2 = 0; m2 < NRIM; m2++) {
            const float sv = s2[m2 * 2];
            if (sv > sn || (sv == sn && m2 < n)) rank++;
        }
        const float mk = (rank < TOPK) ? 1.0f : 0.0f;
        sm[n] = mk;
        g_mask[b * NRIM + n] = mk;
        const float a0 = s2[n * 2], a1 = s2[n * 2 + 1];
        const float mx = fmaxf(a0, a1);
        const float e0 = expf(a0 - mx), e1 = expf(a1 - mx);
        const float inv = 1.0f / (e0 + e1);
        sp0[n] = e0 * inv;
        sp1[n] = e1 * inv;
    }
    __syncthreads();

    for (int v2 = t; v2 < 208; v2 += 128) {
        float v20a = 0.f, v21a = 0.f, v20b = 0.f, v21b = 0.f;
        if (v2 < 200) {
            const int v = 2 * v2;
            v20a = 0.5f * (g_vx[b * 800 + v]     + g_vx[b * 800 + 400 + v]);
            v21a = 0.5f * (vb[v]     + vb[400 + v]);
            v20b = 0.5f * (g_vx[b * 800 + v + 1] + g_vx[b * 800 + 401 + v]);
            v21b = 0.5f * (vb[v + 1] + vb[401 + v]);
        }
#pragma unroll
        for (int n = 0; n < NRIM; n++) {
            const float va = sm[n] * (sp0[n] * v20a + sp1[n] * v21a);
            const float vbv = sm[n] * (sp0[n] * v20b + sp1[n] * v21b);
            __half2 h = __floats2half2_rn(va, vbv);
            uint32_t u; memcpy(&u, &h, 4);
            g_rnnh[(b * NRIM + n) * 208 + v2] = u;
        }
    }
}

// ---------------- communication attention (reads merged ckqv, half ctx out) ----
__global__ void __launch_bounds__(128) cattn_kernel()
{
    const int b = blockIdx.x;
    const int t = threadIdx.x;
    __shared__ float sk[NRIM * 128], sq[NRIM * 128], sv[NRIM * 400];
    __shared__ float sm[NRIM], sc[144], sp[144];

    for (int i = t; i < NRIM * 128; i += 128) {
        const int n = i >> 7, k = i & 127;
        sk[i] = g_ckqv[((long)b * NRIM + n) * 768 + k];
        sq[i] = g_ckqv[((long)b * NRIM + n) * 768 + 128 + k];
    }
    for (int i = t; i < NRIM * 400; i += 128) {
        const int n = i / 400, r = i % 400;
        sv[i] = g_ckqv[((long)b * NRIM + n) * 768 + 256 + r];
    }
    if (t < NRIM) sm[t] = g_mask[b * NRIM + t];
    __syncthreads();

    for (int d = t; d < 144; d += 128) {
        const int h = d / 36, r = d % 36, n = r / 6, m = r % 6;
        float s = 0.f;
#pragma unroll
        for (int k = 0; k < CKS; k++)
            s += sq[n * 128 + h * CKS + k] * sk[m * 128 + h * CKS + k];
        sc[d] = s * 0.17677669529663687f;
    }
    __syncthreads();

    if (t < 24) {
        const int h = t / 6, n = t % 6;
        float mx = -1e30f;
        for (int m = 0; m < 6; m++) mx = fmaxf(mx, sc[h * 36 + n * 6 + m]);
        float e[6], sum = 0.f;
        for (int m = 0; m < 6; m++) { e[m] = expf(sc[h * 36 + n * 6 + m] - mx); sum += e[m]; }
        const float inv = sm[n] / sum;
        for (int m = 0; m < 6; m++) sp[h * 36 + n * 6 + m] = e[m] * inv;
    }
    __syncthreads();

    for (int idx = t; idx < NRIM * 400; idx += 128) {
        const int n = idx / 400, r = idx % 400, h = r / 100;
        float a = 0.f;
#pragma unroll
        for (int m = 0; m < 6; m++) a += sp[h * 36 + n * 6 + m] * sv[m * 400 + r];
        g_ctxh[((long)b * NRIM + n) * 416 + r] = __float2half(a);
    }
    if (t < 96) {
        const int n = t >> 4, r = 400 + (t & 15);
        g_ctxh[((long)b * NRIM + n) * 416 + r] = __float2half(0.f);
    }
}

// -------------------------------------------------------------------------------
extern "C" void kernel_launch(void* const* d_in, const int* in_sizes, int n_in,
                              void* d_out, int out_size)
{
    const float* x     = (const float*)d_in[0];
    const float* hs    = (const float*)d_in[1];
    const float* cs    = (const float*)d_in[2];
    const float* keyW  = (const float*)d_in[3];
    const float* keyb  = (const float*)d_in[4];
    const float* valW  = (const float*)d_in[5];
    const float* valb  = (const float*)d_in[6];
    const float* qW    = (const float*)d_in[7];
    const float* i2h   = (const float*)d_in[8];
    const float* h2h   = (const float*)d_in[9];
    const float* WkC   = (const float*)d_in[10];
    const float* WvC   = (const float*)d_in[11];
    const float* WqC   = (const float*)d_in[12];
    const float* WoC   = (const float*)d_in[13];
    float* out = (float*)d_out;

    float *kx, *q, *vx, *ckqv, *mask, *hnewf;
    uint32_t *xh, *hsh, *rnnh, *wh_val, *wh_pre, *wh_kqv, *wh_o;
    __half *hnewh, *ctxh;
    cudaGetSymbolAddress((void**)&kx,    g_kx);
    cudaGetSymbolAddress((void**)&q,     g_q);
    cudaGetSymbolAddress((void**)&vx,    g_vx);
    cudaGetSymbolAddress((void**)&ckqv,  g_ckqv);
    cudaGetSymbolAddress((void**)&mask,  g_mask);
    cudaGetSymbolAddress((void**)&hnewf, g_hnew);
    cudaGetSymbolAddress((void**)&xh,    g_xh);
    cudaGetSymbolAddress((void**)&hsh,   g_hsh);
    cudaGetSymbolAddress((void**)&rnnh,  g_rnnh);
    cudaGetSymbolAddress((void**)&hnewh, g_hnewh);
    cudaGetSymbolAddress((void**)&ctxh,  g_ctxh);
    cudaGetSymbolAddress((void**)&wh_val, g_wh_val);
    cudaGetSymbolAddress((void**)&wh_pre, g_wh_pre);
    cudaGetSymbolAddress((void**)&wh_kqv, g_wh_kqv);
    cudaGetSymbolAddress((void**)&wh_o,   g_wh_o);

    cudaFuncSetAttribute(gemm_fp16h, cudaFuncAttributeMaxDynamicSharedMemorySize, GSM_STAGE);

    // ---- converts + weight packs ----
    f2h<<<(BSZ * 256 + 255) / 256, 256>>>((const float2*)x,  xh,  BSZ * 256);
    f2h<<<(BSZ * 768 + 255) / 256, 256>>>((const float2*)hs, hsh, BSZ * 768);
    pack_w<<<896, 256>>>(valW, 512, 800, 0, nullptr, 0, 0, 0,
                         wh_val, 800, 896, 512, 0);
    pack_pre<<<dim3(1344, 1, NRIM), 256>>>(i2h, h2h, wh_pre);
    pack_kqv<<<dim3(384, 1, NRIM), 256>>>(WkC, WqC, WvC, wh_kqv);
    pack_w<<<dim3(208, 1, NRIM), 256>>>(WoC, 400, 256, 400L * 256, nullptr, 0, 0, 0,
                                        wh_o, 256, 256, 416, 208L * 256);

    // 1) kx = x @ key_W + key_b  (fp32: feeds top-k signal)
    gemm128<<<dim3(1, 64, 1), 256>>>(x, keyW, keyb, kx, 128, 512, 512, 128, 128, 0, 0, 0, 0);
    // 2) vx = x @ value_W + value_b  (fp16, ep=0)
    gemm_fp16h<<<dim3(7, 64, 1), 256, GSM_PIPE>>>(xh, 256, 256, 0, xh, 256, 0,
                                                  wh_val, 896, 0, 256, valb, vx, 800, 800, 0,
                                                  0, nullptr, nullptr, nullptr, nullptr, nullptr, nullptr);
    // 3) q = hs @ query_W[n]  (fp32: feeds top-k signal)
    gemm128<<<dim3(1, 64, NRIM), 256>>>(hs, qW, nullptr, q, 128, 256, NRIM * UNITS, 128,
                                        NRIM * 128, UNITS, 256L * 128, 128, 0);
    // 4) input attention + top-k + rnn_in (half)
    attn_kernel<<<BSZ, 128>>>(keyb, valb);
    // 5+6+7) preact GEMM + fused LSTM epilogue (ep=1; writes hnew/hnewh/out_c)
    gemm_fp16h<<<dim3(8, 64, NRIM), 256, GSM_STAGE>>>(rnnh, 208, NRIM * 208, 208,
                                                      hsh, 768, 128,
                                                      wh_pre, 1024, 336L * 1024, 336,
                                                      nullptr, nullptr, 1024, 0, 0,
                                                      1, cs, out, mask, hnewf, hnewh, nullptr);
    // 8) ck|cq|cv = h_new @ [Wk|Wq|Wv]  (fp16, ep=0)
    gemm_fp16h<<<dim3(6, 64, NRIM), 256, GSM_PIPE>>>((uint32_t*)hnewh, 128, NRIM * 128, 128,
                                                     (uint32_t*)hnewh, 128, 128,
                                                     wh_kqv, 768, 128L * 768, 128,
                                                     nullptr, ckqv, 768, NRIM * 768, 768,
                                                     0, nullptr, nullptr, nullptr, nullptr, nullptr, nullptr);
    // 9) communication attention -> ctx (half)
    cattn_kernel<<<BSZ, 128>>>();
    // 10+11) hcm GEMM + fused final-h epilogue (ep=2; writes out[0..BF), [BF..2BF))
    gemm_fp16h<<<dim3(2, 64, NRIM), 256, GSM_PIPE>>>((uint32_t*)ctxh, 208, NRIM * 208, 208,
                                                     (uint32_t*)ctxh, 208, 208,
                                                     wh_o, 256, 208L * 256, 208,
                                                     nullptr, nullptr, 256, 0, 0,
                                                     2, nullptr, out, mask, hnewf, nullptr, hs);
}

// round 14
// speedup vs baseline: 1.4996x; 1.4996x over previous
#include <cuda_runtime.h>
#include <cuda_fp16.h>
#include <math.h>
#include <stdint.h>
#include <string.h>

#define BSZ   8192
#define DD    512
#define UNITS 256
#define NRIM  6
#define TOPK  4
#define NIH   2
#define IKS   64
#define IVS   400
#define NCH   4
#define CKS   32
#define CVS   100

#define BF (BSZ*NRIM*UNITS)
#define GSM_PIPE 56832   // 3 stages * (128*20 + 16*136) u32 * 4B; >= 64*132*4 staging

// ---------------- scratch ------------------------------------------------------
__device__ float g_kx  [BSZ*128];
__device__ float g_vx  [BSZ*800];
__device__ float g_q   [BSZ*NRIM*128];
__device__ float g_mask[BSZ*NRIM];
__device__ float g_hnew[BF];
__device__ float g_ckqv[BSZ*NRIM*768];       // [k 0:128 | q 128:256 | v 256:656 | pad]
// half A-side operands
__device__ uint32_t g_xh   [BSZ*256];
__device__ uint32_t g_hsh  [BSZ*768];
__device__ uint32_t g_rnnh [BSZ*NRIM*208];
__device__ __half   g_hnewh[BF];
__device__ __half   g_ctxh [BSZ*NRIM*416];
// packed half2 weights, layout [k/2][Npad], zero-padded
__device__ uint32_t g_wh_val[256*896];
__device__ uint32_t g_wh_pre[6*336*1024];    // gate-interleaved cols: n' = u*4+gate
__device__ uint32_t g_wh_kqv[6*128*768];
__device__ uint32_t g_wh_o  [6*208*256];

// ---------------- fp32 -> half2 convert ---------------------------------------
__global__ void f2h(const float2* __restrict__ src, uint32_t* __restrict__ dst, int n)
{
    const int i = blockIdx.x * 256 + threadIdx.x;
    if (i >= n) return;
    float2 v = src[i];
    __half2 h = __floats2half2_rn(v.x, v.y);
    uint32_t u; memcpy(&u, &h, 4);
    dst[i] = u;
}

// ---------------- weight pack --------------------------------------------------
__global__ void pack_w(const float* __restrict__ W1, int K1, int ldw1, long sW1,
                       const float* __restrict__ W2, int K2, int ldw2, long sW2,
                       uint32_t* __restrict__ Wh, int N, int Npad, int Ktot, long sWh)
{
    const int z = blockIdx.z;
    const long idx = (long)blockIdx.x * 256 + threadIdx.x;
    const int rows = Ktot / 2;
    if (idx >= (long)rows * Npad) return;
    const int k2 = (int)(idx / Npad);
    const int n  = (int)(idx % Npad);
    const int K1p = (K1 + 31) & ~31;

    float v[2];
#pragma unroll
    for (int e = 0; e < 2; e++) {
        const int k = 2 * k2 + e;
        float x = 0.f;
        if (n < N) {
            if (k < K1p) { if (k < K1) x = W1[(long)z * sW1 + (long)k * ldw1 + n]; }
            else { const int ks = k - K1p; if (ks < K2) x = W2[(long)z * sW2 + (long)ks * ldw2 + n]; }
        }
        v[e] = x;
    }
    __half2 h = __float22half2_rn(make_float2(v[0], v[1]));
    uint32_t u; memcpy(&u, &h, 4);
    Wh[(long)z * sWh + idx] = u;
}

// ---------------- preact weight pack: gate-interleaved cols --------------------
__global__ void pack_pre(const float* __restrict__ i2h, const float* __restrict__ h2h,
                         uint32_t* __restrict__ Wh)
{
    const int z = blockIdx.z;
    const int idx = blockIdx.x * 256 + threadIdx.x;    // 0..344063
    const int k2 = idx >> 10, np = idx & 1023;
    const int u = np >> 2, gte = np & 3;
    const int n = gte * 256 + u;
    float v[2];
#pragma unroll
    for (int e = 0; e < 2; e++) {
        const int k = 2 * k2 + e;
        float x = 0.f;
        if (k < 416) { if (k < 400) x = i2h[((long)z * 400 + k) * 1024 + n]; }
        else         { x = h2h[((long)z * 256 + (k - 416)) * 1024 + n]; }
        v[e] = x;
    }
    __half2 h = __float22half2_rn(make_float2(v[0], v[1]));
    uint32_t u32v; memcpy(&u32v, &h, 4);
    Wh[(long)z * (336L * 1024) + idx] = u32v;
}

// ---------------- merged comm weight pack --------------------------------------
__global__ void pack_kqv(const float* __restrict__ Wk, const float* __restrict__ Wq,
                         const float* __restrict__ Wv, uint32_t* __restrict__ Wh)
{
    const int z = blockIdx.z;
    const int idx = blockIdx.x * 256 + threadIdx.x;
    const int k2 = idx / 768, n = idx % 768;
    float v[2];
#pragma unroll
    for (int e = 0; e < 2; e++) {
        const int k = 2 * k2 + e;
        float x = 0.f;
        if (n < 128)      x = Wk[((long)z * 256 + k) * 128 + n];
        else if (n < 256) x = Wq[((long)z * 256 + k) * 128 + (n - 128)];
        else if (n < 656) x = Wv[((long)z * 256 + k) * 400 + (n - 256)];
        v[e] = x;
    }
    __half2 h = __float22half2_rn(make_float2(v[0], v[1]));
    uint32_t u; memcpy(&u, &h, 4);
    Wh[(long)z * (128L * 768) + idx] = u;
}

// =================== fp16 tensor-core GEMM (templated epilogue) ===============
__device__ __forceinline__ void mma_fp16(float* d, const uint32_t* a, const uint32_t* b) {
    asm volatile(
        "mma.sync.aligned.m16n8k16.row.col.f32.f16.f16.f32 "
        "{%0,%1,%2,%3}, {%4,%5,%6,%7}, {%8,%9}, {%0,%1,%2,%3};\n"
        : "+f"(d[0]), "+f"(d[1]), "+f"(d[2]), "+f"(d[3])
        : "r"(a[0]), "r"(a[1]), "r"(a[2]), "r"(a[3]),
          "r"(b[0]), "r"(b[1]));
}
__device__ __forceinline__ void cpa16(uint32_t dst, const void* src) {
    asm volatile("cp.async.ca.shared.global [%0], [%1], 16;\n" :: "r"(dst), "l"(src));
}
#define CP_COMMIT() asm volatile("cp.async.commit_group;\n" ::: "memory")
#define CP_WAIT1()  asm volatile("cp.async.wait_group 1;\n" ::: "memory")
#define CP_WAIT0()  asm volatile("cp.async.wait_group 0;\n" ::: "memory")

__device__ __forceinline__ float sigf(float x) { return 1.f / (1.f + expf(-x)); }

// stage layout (u32): A [128][20] at +0, W [16][136] at +2560; stage stride 4736
template <int EP>
__global__ void __launch_bounds__(256) gemm_fp16h(
    const uint32_t* __restrict__ A1, int K1u, int lda1, long sA1,
    const uint32_t* __restrict__ A2, int lda2, long sA2,
    const uint32_t* __restrict__ Wh, int ldwh, long sWh, int Ktotu,
    const float* __restrict__ bias, float* __restrict__ C, int N, int ldc, long sC,
    const float* __restrict__ cs, float* __restrict__ outp,
    const float* __restrict__ mask, float* __restrict__ hnew,
    __half* __restrict__ hnewh, const float* __restrict__ hs)
{
    extern __shared__ uint32_t sm[];

    const int tid = threadIdx.x, wid = tid >> 5, lane = tid & 31;
    const int warp_m = (wid & 1) * 64, warp_n = (wid >> 1) * 32;
    const int g = lane >> 2, qd = lane & 3;
    const int m0 = blockIdx.y * 128, n0 = blockIdx.x * 128, z = blockIdx.z;
    A1 += (long)z * sA1;
    A2 += (long)z * sA2;
    Wh += (long)z * sWh;
    if (C) C += (long)z * sC;

    const uint32_t smb = (uint32_t)__cvta_generic_to_shared(sm);
    const int aRow = tid >> 1, aC0 = tid & 1;

    auto issue = [&](int t) {
        const int buf = t % 3;
        const uint32_t sA = smb + (uint32_t)buf * 4736u * 4u;
        const uint32_t sW = sA + 2560u * 4u;
        const int ku0 = t * 16;
#pragma unroll
        for (int c = 0; c < 2; c++) {
            const int o = ku0 + (aC0 + 2 * c) * 4;
            const uint32_t* src = (o < K1u) ? A1 + (long)(m0 + aRow) * lda1 + o
                                            : A2 + (long)(m0 + aRow) * lda2 + (o - K1u);
            cpa16(sA + (uint32_t)(aRow * 20 + (aC0 + 2 * c) * 4) * 4u, src);
        }
#pragma unroll
        for (int i = 0; i < 2; i++) {
            const int idx = i * 256 + tid;
            const int r = idx >> 5, cu = (idx & 31) * 4;
            cpa16(sW + (uint32_t)(r * 136 + cu) * 4u,
                  Wh + (long)(ku0 + r) * ldwh + n0 + cu);
        }
    };

    float acc[4][4][4];
#pragma unroll
    for (int i = 0; i < 4; i++)
#pragma unroll
        for (int j = 0; j < 4; j++)
#pragma unroll
            for (int r = 0; r < 4; r++) acc[i][j][r] = 0.f;

    const int T = Ktotu / 16;
    issue(0); CP_COMMIT();
    issue(1); CP_COMMIT();

    for (int t = 0; t < T; t++) {
        CP_WAIT1();
        __syncthreads();
        if (t + 2 < T) issue(t + 2);
        CP_COMMIT();

        const uint32_t* Asb = sm + (t % 3) * 4736;
        const uint32_t* Wsb = Asb + 2560;
#pragma unroll
        for (int ks2 = 0; ks2 < 2; ks2++) {
            const int kb = ks2 * 8;
            uint32_t af[4][4], bf[4][2];
#pragma unroll
            for (int i = 0; i < 4; i++) {
                const int mb = warp_m + i * 16 + g;
                af[i][0] = Asb[mb * 20 + kb + qd];
                af[i][1] = Asb[(mb + 8) * 20 + kb + qd];
                af[i][2] = Asb[mb * 20 + kb + qd + 4];
                af[i][3] = Asb[(mb + 8) * 20 + kb + qd + 4];
            }
#pragma unroll
            for (int j = 0; j < 4; j++) {
                const int nb = warp_n + j * 8 + g;
                bf[j][0] = Wsb[(kb + qd) * 136 + nb];
                bf[j][1] = Wsb[(kb + qd + 4) * 136 + nb];
            }
#pragma unroll
            for (int i = 0; i < 4; i++)
#pragma unroll
                for (int j = 0; j < 4; j++)
                    mma_fp16(acc[i][j], af[i], bf[j]);
        }
    }

    if (EP == 0) {
        // ---- plain epilogue ----
#pragma unroll
        for (int i = 0; i < 4; i++) {
            const long mA = m0 + warp_m + i * 16 + g;
            const long mB = mA + 8;
#pragma unroll
            for (int j = 0; j < 4; j++) {
                const int n = n0 + warp_n + j * 8 + qd * 2;
#pragma unroll
                for (int e = 0; e < 2; e++) {
                    const int col = n + e;
                    if (col < N) {
                        float vA = acc[i][j][e];
                        float vB = acc[i][j][2 + e];
                        if (bias) { vA += bias[col]; vB += bias[col]; }
                        C[mA * ldc + col] = vA;
                        C[mB * ldc + col] = vB;
                    }
                }
            }
        }
    } else if (EP == 1) {
        // ---- LSTM epilogue, two 64-row phases (stg fits in pipeline smem) ----
        CP_WAIT0();
        __syncthreads();
        float* stg = (float*)sm;        // [64][132]
#pragma unroll
        for (int ph = 0; ph < 2; ph++) {
            if (warp_m == ph * 64) {
#pragma unroll
                for (int i = 0; i < 4; i++) {
                    const int rA = i * 16 + g, rB = rA + 8;   // local rows 0..63
#pragma unroll
                    for (int j = 0; j < 4; j++) {
                        const int cl = warp_n + j * 8 + qd * 2;
                        stg[rA * 132 + cl]     = acc[i][j][0];
                        stg[rA * 132 + cl + 1] = acc[i][j][1];
                        stg[rB * 132 + cl]     = acc[i][j][2];
                        stg[rB * 132 + cl + 1] = acc[i][j][3];
                    }
                }
            }
            __syncthreads();
            for (int s = tid; s < 64 * 32; s += 256) {
                const int row = ph * 64 + (s >> 5), uu = s & 31;
                float4 gt = *(const float4*)&stg[(s >> 5) * 132 + uu * 4];
                const long bn = (long)(m0 + row) * NRIM + z;
                const long i  = bn * 256 + (n0 >> 2) + uu;
                const float nc = tanhf(gt.x);
                const float ig = sigf(gt.y);
                const float fg = sigf(gt.z);
                const float og = sigf(gt.w);
                const float cold = cs[i];
                const float c = cold * fg + ig * nc;
                const float h = og * tanhf(c);
                hnew[i]  = h;
                hnewh[i] = __float2half(h);
                outp[2L * BF + i] = (mask[bn] != 0.f) ? c : cold;
            }
            __syncthreads();
        }
    } else {
        // ---- final-h epilogue: h = mask ? acc+hnew : hs ----
#pragma unroll
        for (int i = 0; i < 4; i++) {
            const long mA = m0 + warp_m + i * 16 + g;
            const long mB = mA + 8;
            const long bnA = mA * NRIM + z, bnB = mB * NRIM + z;
            const float mkA = mask[bnA], mkB = mask[bnB];
#pragma unroll
            for (int j = 0; j < 4; j++) {
                const int col = n0 + warp_n + j * 8 + qd * 2;
#pragma unroll
                for (int e = 0; e < 2; e++) {
                    const long iA = bnA * 256 + col + e;
                    const long iB = bnB * 256 + col + e;
                    const float hA = (mkA != 0.f) ? (acc[i][j][e] + hnew[iA]) : hs[iA];
                    const float hB = (mkB != 0.f) ? (acc[i][j][2 + e] + hnew[iB]) : hs[iB];
                    outp[iA] = hA; outp[BF + iA] = hA;
                    outp[iB] = hB; outp[BF + iB] = hB;
                }
            }
        }
    }
}

// =================== fp32 GEMM (top-k-sensitive path only) ====================
__global__ void __launch_bounds__(256) gemm128(
    const float* __restrict__ A, const float* __restrict__ W,
    const float* __restrict__ bias, float* __restrict__ C,
    int N, int Kd, int lda, int ldw, int ldc,
    long sA, long sW, long sC, int accum)
{
    A += (long)blockIdx.z * sA;
    W += (long)blockIdx.z * sW;
    C += (long)blockIdx.z * sC;

    __shared__ float As[8][128];
    __shared__ float Ws[8][128];

    const int tid = threadIdx.x;
    const int m0  = blockIdx.y * 128;
    const int n0  = blockIdx.x * 128;

    const int aRow = tid >> 1;
    const int aK   = (tid & 1) * 4;
    const int wK   = tid >> 5;
    const int wC   = (tid & 31) * 4;
    const int ty   = tid >> 4;
    const int tx   = tid & 15;

    float acc[8][8];
#pragma unroll
    for (int i = 0; i < 8; i++)
#pragma unroll
        for (int j = 0; j < 8; j++) acc[i][j] = 0.f;

    const float* Aptr = A + (long)(m0 + aRow) * lda + aK;

    for (int k0 = 0; k0 < Kd; k0 += 8) {
        float4 av = *(const float4*)(Aptr + k0);
        As[aK + 0][aRow] = av.x;
        As[aK + 1][aRow] = av.y;
        As[aK + 2][aRow] = av.z;
        As[aK + 3][aRow] = av.w;
        {
            const int col = n0 + wC;
            const float* wp = W + (long)(k0 + wK) * ldw;
            if (col + 3 < N) {
                *(float4*)&Ws[wK][wC] = *(const float4*)(wp + col);
            } else {
#pragma unroll
                for (int j = 0; j < 4; j++)
                    Ws[wK][wC + j] = (col + j < N) ? wp[col + j] : 0.f;
            }
        }
        __syncthreads();

#pragma unroll
        for (int kk = 0; kk < 8; kk++) {
            float a[8], bq[8];
            *(float4*)(a)      = *(const float4*)&As[kk][ty * 8];
            *(float4*)(a + 4)  = *(const float4*)&As[kk][ty * 8 + 4];
            *(float4*)(bq)     = *(const float4*)&Ws[kk][tx * 8];
            *(float4*)(bq + 4) = *(const float4*)&Ws[kk][tx * 8 + 4];
#pragma unroll
            for (int i = 0; i < 8; i++)
#pragma unroll
                for (int j = 0; j < 8; j++)
                    acc[i][j] += a[i] * bq[j];
        }
        __syncthreads();
    }

#pragma unroll
    for (int i = 0; i < 8; i++) {
        const long row = m0 + ty * 8 + i;
#pragma unroll
        for (int j = 0; j < 8; j++) {
            const int col = n0 + tx * 8 + j;
            if (col < N) {
                float v = acc[i][j];
                if (bias)  v += bias[col];
                if (accum) v += C[row * ldc + col];
                C[row * ldc + col] = v;
            }
        }
    }
}

// ---------------- input attention + top-k mask + rnn_in (half out) -------------
__global__ void __launch_bounds__(128) attn_kernel(const float* __restrict__ kb,
                                                   const float* __restrict__ vb)
{
    const int b = blockIdx.x;
    const int t = threadIdx.x;
    __shared__ float sq[NRIM * 128], skx[128], skb[128];
    __shared__ float s2[12], sm[NRIM], sp0[NRIM], sp1[NRIM];

    for (int i = t; i < NRIM * 128; i += 128) sq[i] = g_q[b * NRIM * 128 + i];
    if (t < 128) { skx[t] = g_kx[b * 128 + t]; skb[t] = kb[t]; }
    __syncthreads();

    const int w = t >> 5, lane = t & 31;
    for (int d = w; d < 12; d += 4) {
        const int n = d >> 1, m = d & 1;
        const float* kv = m ? skb : skx;
        float s = 0.f;
        for (int k = lane; k < 128; k += 32) s += sq[n * 128 + k] * kv[k];
#pragma unroll
        for (int o = 16; o; o >>= 1) s += __shfl_xor_sync(0xffffffffu, s, o);
        if (!lane) s2[d] = s * (1.0f / 16.0f);
    }
    __syncthreads();

    if (t < NRIM) {
        const int n = t;
        const float sn = s2[n * 2];
        int rank = 0;
        for (int m2 = 0; m2 < NRIM; m2++) {
            const float sv = s2[m2 * 2];
            if (sv > sn || (sv == sn && m2 < n)) rank++;
        }
        const float mk = (rank < TOPK) ? 1.0f : 0.0f;
        sm[n] = mk;
        g_mask[b * NRIM + n] = mk;
        const float a0 = s2[n * 2], a1 = s2[n * 2 + 1];
        const float mx = fmaxf(a0, a1);
        const float e0 = expf(a0 - mx), e1 = expf(a1 - mx);
        const float inv = 1.0f / (e0 + e1);
        sp0[n] = e0 * inv;
        sp1[n] = e1 * inv;
    }
    __syncthreads();

    for (int v2 = t; v2 < 208; v2 += 128) {
        float v20a = 0.f, v21a = 0.f, v20b = 0.f, v21b = 0.f;
        if (v2 < 200) {
            const int v = 2 * v2;
            v20a = 0.5f * (g_vx[b * 800 + v]     + g_vx[b * 800 + 400 + v]);
            v21a = 0.5f * (vb[v]     + vb[400 + v]);
            v20b = 0.5f * (g_vx[b * 800 + v + 1] + g_vx[b * 800 + 401 + v]);
            v21b = 0.5f * (vb[v + 1] + vb[401 + v]);
        }
#pragma unroll
        for (int n = 0; n < NRIM; n++) {
            const float va = sm[n] * (sp0[n] * v20a + sp1[n] * v21a);
            const float vbv = sm[n] * (sp0[n] * v20b + sp1[n] * v21b);
            __half2 h = __floats2half2_rn(va, vbv);
            uint32_t u; memcpy(&u, &h, 4);
            g_rnnh[(b * NRIM + n) * 208 + v2] = u;
        }
    }
}

// ---------------- communication attention (reads merged ckqv, half ctx out) ----
__global__ void __launch_bounds__(128) cattn_kernel()
{
    const int b = blockIdx.x;
    const int t = threadIdx.x;
    __shared__ float sk[NRIM * 128], sq[NRIM * 128], sv[NRIM * 400];
    __shared__ float sm[NRIM], sc[144], sp[144];

    for (int i = t; i < NRIM * 128; i += 128) {
        const int n = i >> 7, k = i & 127;
        sk[i] = g_ckqv[((long)b * NRIM + n) * 768 + k];
        sq[i] = g_ckqv[((long)b * NRIM + n) * 768 + 128 + k];
    }
    for (int i = t; i < NRIM * 400; i += 128) {
        const int n = i / 400, r = i % 400;
        sv[i] = g_ckqv[((long)b * NRIM + n) * 768 + 256 + r];
    }
    if (t < NRIM) sm[t] = g_mask[b * NRIM + t];
    __syncthreads();

    for (int d = t; d < 144; d += 128) {
        const int h = d / 36, r = d % 36, n = r / 6, m = r % 6;
        float s = 0.f;
#pragma unroll
        for (int k = 0; k < CKS; k++)
            s += sq[n * 128 + h * CKS + k] * sk[m * 128 + h * CKS + k];
        sc[d] = s * 0.17677669529663687f;
    }
    __syncthreads();

    if (t < 24) {
        const int h = t / 6, n = t % 6;
        float mx = -1e30f;
        for (int m = 0; m < 6; m++) mx = fmaxf(mx, sc[h * 36 + n * 6 + m]);
        float e[6], sum = 0.f;
        for (int m = 0; m < 6; m++) { e[m] = expf(sc[h * 36 + n * 6 + m] - mx); sum += e[m]; }
        const float inv = sm[n] / sum;
        for (int m = 0; m < 6; m++) sp[h * 36 + n * 6 + m] = e[m] * inv;
    }
    __syncthreads();

    for (int idx = t; idx < NRIM * 400; idx += 128) {
        const int n = idx / 400, r = idx % 400, h = r / 100;
        float a = 0.f;
#pragma unroll
        for (int m = 0; m < 6; m++) a += sp[h * 36 + n * 6 + m] * sv[m * 400 + r];
        g_ctxh[((long)b * NRIM + n) * 416 + r] = __float2half(a);
    }
    if (t < 96) {
        const int n = t >> 4, r = 400 + (t & 15);
        g_ctxh[((long)b * NRIM + n) * 416 + r] = __float2half(0.f);
    }
}

// -------------------------------------------------------------------------------
extern "C" void kernel_launch(void* const* d_in, const int* in_sizes, int n_in,
                              void* d_out, int out_size)
{
    const float* x     = (const float*)d_in[0];
    const float* hs    = (const float*)d_in[1];
    const float* cs    = (const float*)d_in[2];
    const float* keyW  = (const float*)d_in[3];
    const float* keyb  = (const float*)d_in[4];
    const float* valW  = (const float*)d_in[5];
    const float* valb  = (const float*)d_in[6];
    const float* qW    = (const float*)d_in[7];
    const float* i2h   = (const float*)d_in[8];
    const float* h2h   = (const float*)d_in[9];
    const float* WkC   = (const float*)d_in[10];
    const float* WvC   = (const float*)d_in[11];
    const float* WqC   = (const float*)d_in[12];
    const float* WoC   = (const float*)d_in[13];
    float* out = (float*)d_out;

    float *kx, *q, *vx, *ckqv, *mask, *hnewf;
    uint32_t *xh, *hsh, *rnnh, *wh_val, *wh_pre, *wh_kqv, *wh_o;
    __half *hnewh, *ctxh;
    cudaGetSymbolAddress((void**)&kx,    g_kx);
    cudaGetSymbolAddress((void**)&q,     g_q);
    cudaGetSymbolAddress((void**)&vx,    g_vx);
    cudaGetSymbolAddress((void**)&ckqv,  g_ckqv);
    cudaGetSymbolAddress((void**)&mask,  g_mask);
    cudaGetSymbolAddress((void**)&hnewf, g_hnew);
    cudaGetSymbolAddress((void**)&xh,    g_xh);
    cudaGetSymbolAddress((void**)&hsh,   g_hsh);
    cudaGetSymbolAddress((void**)&rnnh,  g_rnnh);
    cudaGetSymbolAddress((void**)&hnewh, g_hnewh);
    cudaGetSymbolAddress((void**)&ctxh,  g_ctxh);
    cudaGetSymbolAddress((void**)&wh_val, g_wh_val);
    cudaGetSymbolAddress((void**)&wh_pre, g_wh_pre);
    cudaGetSymbolAddress((void**)&wh_kqv, g_wh_kqv);
    cudaGetSymbolAddress((void**)&wh_o,   g_wh_o);

    cudaFuncSetAttribute(gemm_fp16h<0>, cudaFuncAttributeMaxDynamicSharedMemorySize, GSM_PIPE);
    cudaFuncSetAttribute(gemm_fp16h<1>, cudaFuncAttributeMaxDynamicSharedMemorySize, GSM_PIPE);
    cudaFuncSetAttribute(gemm_fp16h<2>, cudaFuncAttributeMaxDynamicSharedMemorySize, GSM_PIPE);

    // ---- converts + weight packs ----
    f2h<<<(BSZ * 256 + 255) / 256, 256>>>((const float2*)x,  xh,  BSZ * 256);
    f2h<<<(BSZ * 768 + 255) / 256, 256>>>((const float2*)hs, hsh, BSZ * 768);
    pack_w<<<896, 256>>>(valW, 512, 800, 0, nullptr, 0, 0, 0,
                         wh_val, 800, 896, 512, 0);
    pack_pre<<<dim3(1344, 1, NRIM), 256>>>(i2h, h2h, wh_pre);
    pack_kqv<<<dim3(384, 1, NRIM), 256>>>(WkC, WqC, WvC, wh_kqv);
    pack_w<<<dim3(208, 1, NRIM), 256>>>(WoC, 400, 256, 400L * 256, nullptr, 0, 0, 0,
                                        wh_o, 256, 256, 416, 208L * 256);

    // 1) kx = x @ key_W + key_b  (fp32: feeds top-k signal)
    gemm128<<<dim3(1, 64, 1), 256>>>(x, keyW, keyb, kx, 128, 512, 512, 128, 128, 0, 0, 0, 0);
    // 2) vx = x @ value_W + value_b  (fp16, EP=0)
    gemm_fp16h<0><<<dim3(7, 64, 1), 256, GSM_PIPE>>>(xh, 256, 256, 0, xh, 256, 0,
                                                     wh_val, 896, 0, 256, valb, vx, 800, 800, 0,
                                                     nullptr, nullptr, nullptr, nullptr, nullptr, nullptr);
    // 3) q = hs @ query_W[n]  (fp32: feeds top-k signal)
    gemm128<<<dim3(1, 64, NRIM), 256>>>(hs, qW, nullptr, q, 128, 256, NRIM * UNITS, 128,
                                        NRIM * 128, UNITS, 256L * 128, 128, 0);
    // 4) input attention + top-k + rnn_in (half)
    attn_kernel<<<BSZ, 128>>>(keyb, valb);
    // 5+6+7) preact GEMM + fused LSTM epilogue (EP=1)
    gemm_fp16h<1><<<dim3(8, 64, NRIM), 256, GSM_PIPE>>>(rnnh, 208, NRIM * 208, 208,
                                                        hsh, 768, 128,
                                                        wh_pre, 1024, 336L * 1024, 336,
                                                        nullptr, nullptr, 1024, 0, 0,
                                                        cs, out, mask, hnewf, hnewh, nullptr);
    // 8) ck|cq|cv = h_new @ [Wk|Wq|Wv]  (fp16, EP=0)
    gemm_fp16h<0><<<dim3(6, 64, NRIM), 256, GSM_PIPE>>>((uint32_t*)hnewh, 128, NRIM * 128, 128,
                                                        (uint32_t*)hnewh, 128, 128,
                                                        wh_kqv, 768, 128L * 768, 128,
                                                        nullptr, ckqv, 768, NRIM * 768, 768,
                                                        nullptr, nullptr, nullptr, nullptr, nullptr, nullptr);
    // 9) communication attention -> ctx (half)
    cattn_kernel<<<BSZ, 128>>>();
    // 10+11) hcm GEMM + fused final-h epilogue (EP=2)
    gemm_fp16h<2><<<dim3(2, 64, NRIM), 256, GSM_PIPE>>>((uint32_t*)ctxh, 208, NRIM * 208, 208,
                                                        (uint32_t*)ctxh, 208, 208,
                                                        wh_o, 256, 208L * 256, 208,
                                                        nullptr, nullptr, 256, 0, 0,
                                                        nullptr, out, mask, hnewf, nullptr, hs);
}

// round 15
// speedup vs baseline: 1.6111x; 1.0744x over previous
#include <cuda_runtime.h>
#include <cuda_fp16.h>
#include <math.h>
#include <stdint.h>
#include <string.h>

#define BSZ   8192
#define DD    512
#define UNITS 256
#define NRIM  6
#define TOPK  4
#define NIH   2
#define IKS   64
#define IVS   400
#define NCH   4
#define CKS   32
#define CVS   100

#define BF (BSZ*NRIM*UNITS)
#define GSM_PIPE 56832   // 3 stages * (128*20 + 16*136) u32 * 4B; >= 64*132*4 staging

// ---------------- scratch ------------------------------------------------------
__device__ float g_kx  [BSZ*128];
__device__ float g_vx  [BSZ*800];
__device__ float g_q   [BSZ*NRIM*128];
__device__ float g_mask[BSZ*NRIM];
__device__ float g_hnew[BF];
__device__ float g_ckqv[BSZ*NRIM*768];       // [k 0:128 | q 128:256 | v 256:656 | pad]
// half A-side operands
__device__ uint32_t g_xh   [BSZ*256];
__device__ uint32_t g_hsh  [BSZ*768];
__device__ uint32_t g_rnnh [BSZ*NRIM*208];
__device__ __half   g_hnewh[BF];
__device__ __half   g_ctxh [BSZ*NRIM*416];
// packed half2 weights, layout [k/2][Npad], zero-padded
__device__ uint32_t g_wh_val[256*896];
__device__ uint32_t g_wh_pre[6*336*1024];    // gate-interleaved cols: n' = u*4+gate
__device__ uint32_t g_wh_kqv[6*128*768];
__device__ uint32_t g_wh_o  [6*208*256];

// ---------------- fp32 -> half2 convert (dual-array fat kernel) ----------------
__global__ void f2h2(const float2* __restrict__ srcA, uint32_t* __restrict__ dstA, int nA,
                     const float2* __restrict__ srcB, uint32_t* __restrict__ dstB, int nB)
{
    const long gi = (long)blockIdx.x * 256 + threadIdx.x;
    const float2* src;
    uint32_t* dst;
    long i;
    if (gi < nA) { src = srcA; dst = dstA; i = gi; }
    else { i = gi - nA; if (i >= nB) return; src = srcB; dst = dstB; }
    float2 v = src[i];
    __half2 h = __floats2half2_rn(v.x, v.y);
    uint32_t u; memcpy(&u, &h, 4);
    dst[i] = u;
}

// ---------------- weight pack --------------------------------------------------
__global__ void pack_w(const float* __restrict__ W1, int K1, int ldw1, long sW1,
                       const float* __restrict__ W2, int K2, int ldw2, long sW2,
                       uint32_t* __restrict__ Wh, int N, int Npad, int Ktot, long sWh)
{
    const int z = blockIdx.z;
    const long idx = (long)blockIdx.x * 256 + threadIdx.x;
    const int rows = Ktot / 2;
    if (idx >= (long)rows * Npad) return;
    const int k2 = (int)(idx / Npad);
    const int n  = (int)(idx % Npad);
    const int K1p = (K1 + 31) & ~31;

    float v[2];
#pragma unroll
    for (int e = 0; e < 2; e++) {
        const int k = 2 * k2 + e;
        float x = 0.f;
        if (n < N) {
            if (k < K1p) { if (k < K1) x = W1[(long)z * sW1 + (long)k * ldw1 + n]; }
            else { const int ks = k - K1p; if (ks < K2) x = W2[(long)z * sW2 + (long)ks * ldw2 + n]; }
        }
        v[e] = x;
    }
    __half2 h = __float22half2_rn(make_float2(v[0], v[1]));
    uint32_t u; memcpy(&u, &h, 4);
    Wh[(long)z * sWh + idx] = u;
}

// ---------------- preact weight pack: gate-interleaved cols --------------------
__global__ void pack_pre(const float* __restrict__ i2h, const float* __restrict__ h2h,
                         uint32_t* __restrict__ Wh)
{
    const int z = blockIdx.z;
    const int idx = blockIdx.x * 256 + threadIdx.x;    // 0..344063
    const int k2 = idx >> 10, np = idx & 1023;
    const int u = np >> 2, gte = np & 3;
    const int n = gte * 256 + u;
    float v[2];
#pragma unroll
    for (int e = 0; e < 2; e++) {
        const int k = 2 * k2 + e;
        float x = 0.f;
        if (k < 416) { if (k < 400) x = i2h[((long)z * 400 + k) * 1024 + n]; }
        else         { x = h2h[((long)z * 256 + (k - 416)) * 1024 + n]; }
        v[e] = x;
    }
    __half2 h = __float22half2_rn(make_float2(v[0], v[1]));
    uint32_t u32v; memcpy(&u32v, &h, 4);
    Wh[(long)z * (336L * 1024) + idx] = u32v;
}

// ---------------- merged comm weight pack --------------------------------------
__global__ void pack_kqv(const float* __restrict__ Wk, const float* __restrict__ Wq,
                         const float* __restrict__ Wv, uint32_t* __restrict__ Wh)
{
    const int z = blockIdx.z;
    const int idx = blockIdx.x * 256 + threadIdx.x;
    const int k2 = idx / 768, n = idx % 768;
    float v[2];
#pragma unroll
    for (int e = 0; e < 2; e++) {
        const int k = 2 * k2 + e;
        float x = 0.f;
        if (n < 128)      x = Wk[((long)z * 256 + k) * 128 + n];
        else if (n < 256) x = Wq[((long)z * 256 + k) * 128 + (n - 128)];
        else if (n < 656) x = Wv[((long)z * 256 + k) * 400 + (n - 256)];
        v[e] = x;
    }
    __half2 h = __float22half2_rn(make_float2(v[0], v[1]));
    uint32_t u; memcpy(&u, &h, 4);
    Wh[(long)z * (128L * 768) + idx] = u;
}

// =================== fp16 tensor-core GEMM (templated epilogue) ===============
__device__ __forceinline__ void mma_fp16(float* d, const uint32_t* a, const uint32_t* b) {
    asm volatile(
        "mma.sync.aligned.m16n8k16.row.col.f32.f16.f16.f32 "
        "{%0,%1,%2,%3}, {%4,%5,%6,%7}, {%8,%9}, {%0,%1,%2,%3};\n"
        : "+f"(d[0]), "+f"(d[1]), "+f"(d[2]), "+f"(d[3])
        : "r"(a[0]), "r"(a[1]), "r"(a[2]), "r"(a[3]),
          "r"(b[0]), "r"(b[1]));
}
__device__ __forceinline__ void cpa16(uint32_t dst, const void* src) {
    asm volatile("cp.async.ca.shared.global [%0], [%1], 16;\n" :: "r"(dst), "l"(src));
}
#define CP_COMMIT() asm volatile("cp.async.commit_group;\n" ::: "memory")
#define CP_WAIT1()  asm volatile("cp.async.wait_group 1;\n" ::: "memory")
#define CP_WAIT0()  asm volatile("cp.async.wait_group 0;\n" ::: "memory")

__device__ __forceinline__ float sigf(float x) { return 1.f / (1.f + expf(-x)); }

// stage layout (u32): A [128][20] at +0, W [16][136] at +2560; stage stride 4736
template <int EP>
__global__ void __launch_bounds__(256) gemm_fp16h(
    const uint32_t* __restrict__ A1, int K1u, int lda1, long sA1,
    const uint32_t* __restrict__ A2, int lda2, long sA2,
    const uint32_t* __restrict__ Wh, int ldwh, long sWh, int Ktotu,
    const float* __restrict__ bias, float* __restrict__ C, int N, int ldc, long sC,
    const float* __restrict__ cs, float* __restrict__ outp,
    const float* __restrict__ mask, float* __restrict__ hnew,
    __half* __restrict__ hnewh, const float* __restrict__ hs)
{
    extern __shared__ uint32_t sm[];

    const int tid = threadIdx.x, wid = tid >> 5, lane = tid & 31;
    const int warp_m = (wid & 1) * 64, warp_n = (wid >> 1) * 32;
    const int g = lane >> 2, qd = lane & 3;
    const int m0 = blockIdx.y * 128, n0 = blockIdx.x * 128, z = blockIdx.z;
    A1 += (long)z * sA1;
    A2 += (long)z * sA2;
    Wh += (long)z * sWh;
    if (C) C += (long)z * sC;

    const uint32_t smb = (uint32_t)__cvta_generic_to_shared(sm);
    const int aRow = tid >> 1, aC0 = tid & 1;

    auto issue = [&](int t) {
        const int buf = t % 3;
        const uint32_t sA = smb + (uint32_t)buf * 4736u * 4u;
        const uint32_t sW = sA + 2560u * 4u;
        const int ku0 = t * 16;
#pragma unroll
        for (int c = 0; c < 2; c++) {
            const int o = ku0 + (aC0 + 2 * c) * 4;
            const uint32_t* src = (o < K1u) ? A1 + (long)(m0 + aRow) * lda1 + o
                                            : A2 + (long)(m0 + aRow) * lda2 + (o - K1u);
            cpa16(sA + (uint32_t)(aRow * 20 + (aC0 + 2 * c) * 4) * 4u, src);
        }
#pragma unroll
        for (int i = 0; i < 2; i++) {
            const int idx = i * 256 + tid;
            const int r = idx >> 5, cu = (idx & 31) * 4;
            cpa16(sW + (uint32_t)(r * 136 + cu) * 4u,
                  Wh + (long)(ku0 + r) * ldwh + n0 + cu);
        }
    };

    float acc[4][4][4];
#pragma unroll
    for (int i = 0; i < 4; i++)
#pragma unroll
        for (int j = 0; j < 4; j++)
#pragma unroll
            for (int r = 0; r < 4; r++) acc[i][j][r] = 0.f;

    const int T = Ktotu / 16;
    issue(0); CP_COMMIT();
    issue(1); CP_COMMIT();

    for (int t = 0; t < T; t++) {
        CP_WAIT1();
        __syncthreads();
        if (t + 2 < T) issue(t + 2);
        CP_COMMIT();

        const uint32_t* Asb = sm + (t % 3) * 4736;
        const uint32_t* Wsb = Asb + 2560;
#pragma unroll
        for (int ks2 = 0; ks2 < 2; ks2++) {
            const int kb = ks2 * 8;
            uint32_t af[4][4], bf[4][2];
#pragma unroll
            for (int i = 0; i < 4; i++) {
                const int mb = warp_m + i * 16 + g;
                af[i][0] = Asb[mb * 20 + kb + qd];
                af[i][1] = Asb[(mb + 8) * 20 + kb + qd];
                af[i][2] = Asb[mb * 20 + kb + qd + 4];
                af[i][3] = Asb[(mb + 8) * 20 + kb + qd + 4];
            }
#pragma unroll
            for (int j = 0; j < 4; j++) {
                const int nb = warp_n + j * 8 + g;
                bf[j][0] = Wsb[(kb + qd) * 136 + nb];
                bf[j][1] = Wsb[(kb + qd + 4) * 136 + nb];
            }
#pragma unroll
            for (int i = 0; i < 4; i++)
#pragma unroll
                for (int j = 0; j < 4; j++)
                    mma_fp16(acc[i][j], af[i], bf[j]);
        }
    }

    if (EP == 0) {
#pragma unroll
        for (int i = 0; i < 4; i++) {
            const long mA = m0 + warp_m + i * 16 + g;
            const long mB = mA + 8;
#pragma unroll
            for (int j = 0; j < 4; j++) {
                const int n = n0 + warp_n + j * 8 + qd * 2;
#pragma unroll
                for (int e = 0; e < 2; e++) {
                    const int col = n + e;
                    if (col < N) {
                        float vA = acc[i][j][e];
                        float vB = acc[i][j][2 + e];
                        if (bias) { vA += bias[col]; vB += bias[col]; }
                        C[mA * ldc + col] = vA;
                        C[mB * ldc + col] = vB;
                    }
                }
            }
        }
    } else if (EP == 1) {
        // ---- LSTM epilogue, two 64-row phases ----
        CP_WAIT0();
        __syncthreads();
        float* stg = (float*)sm;        // [64][132]
#pragma unroll
        for (int ph = 0; ph < 2; ph++) {
            if (warp_m == ph * 64) {
#pragma unroll
                for (int i = 0; i < 4; i++) {
                    const int rA = i * 16 + g, rB = rA + 8;
#pragma unroll
                    for (int j = 0; j < 4; j++) {
                        const int cl = warp_n + j * 8 + qd * 2;
                        stg[rA * 132 + cl]     = acc[i][j][0];
                        stg[rA * 132 + cl + 1] = acc[i][j][1];
                        stg[rB * 132 + cl]     = acc[i][j][2];
                        stg[rB * 132 + cl + 1] = acc[i][j][3];
                    }
                }
            }
            __syncthreads();
            for (int s = tid; s < 64 * 32; s += 256) {
                const int row = ph * 64 + (s >> 5), uu = s & 31;
                float4 gt = *(const float4*)&stg[(s >> 5) * 132 + uu * 4];
                const long bn = (long)(m0 + row) * NRIM + z;
                const long i  = bn * 256 + (n0 >> 2) + uu;
                const float nc = tanhf(gt.x);
                const float ig = sigf(gt.y);
                const float fg = sigf(gt.z);
                const float og = sigf(gt.w);
                const float cold = cs[i];
                const float c = cold * fg + ig * nc;
                const float h = og * tanhf(c);
                hnew[i]  = h;
                hnewh[i] = __float2half(h);
                outp[2L * BF + i] = (mask[bn] != 0.f) ? c : cold;
            }
            __syncthreads();
        }
    } else {
        // ---- final-h epilogue ----
#pragma unroll
        for (int i = 0; i < 4; i++) {
            const long mA = m0 + warp_m + i * 16 + g;
            const long mB = mA + 8;
            const long bnA = mA * NRIM + z, bnB = mB * NRIM + z;
            const float mkA = mask[bnA], mkB = mask[bnB];
#pragma unroll
            for (int j = 0; j < 4; j++) {
                const int col = n0 + warp_n + j * 8 + qd * 2;
#pragma unroll
                for (int e = 0; e < 2; e++) {
                    const long iA = bnA * 256 + col + e;
                    const long iB = bnB * 256 + col + e;
                    const float hA = (mkA != 0.f) ? (acc[i][j][e] + hnew[iA]) : hs[iA];
                    const float hB = (mkB != 0.f) ? (acc[i][j][2 + e] + hnew[iB]) : hs[iB];
                    outp[iA] = hA; outp[BF + iA] = hA;
                    outp[iB] = hB; outp[BF + iB] = hB;
                }
            }
        }
    }
}

// =================== fp32 GEMM, fat kx+q merge (top-k path) ===================
// grid (1, 64, 7): z<6 -> q[:,z,:] = hs[:,z,:]@qW[z]; z==6 -> kx = x@keyW + keyb
__global__ void __launch_bounds__(256) gemm128_fat(
    const float* __restrict__ x,  const float* __restrict__ keyW,
    const float* __restrict__ keyb, float* __restrict__ kx,
    const float* __restrict__ hs, const float* __restrict__ qW,
    float* __restrict__ qout)
{
    const int z = blockIdx.z;
    const float* A; const float* W; const float* bias; float* C;
    int Kd, lda, ldw, ldc;
    if (z < 6) {
        A = hs + z * UNITS; W = qW + (long)z * 256 * 128; bias = nullptr;
        C = qout + z * 128; Kd = 256; lda = NRIM * UNITS; ldw = 128; ldc = NRIM * 128;
    } else {
        A = x; W = keyW; bias = keyb; C = kx;
        Kd = 512; lda = 512; ldw = 128; ldc = 128;
    }

    __shared__ float As[8][128];
    __shared__ float Ws[8][128];

    const int tid = threadIdx.x;
    const int m0  = blockIdx.y * 128;

    const int aRow = tid >> 1;
    const int aK   = (tid & 1) * 4;
    const int wK   = tid >> 5;
    const int wC   = (tid & 31) * 4;
    const int ty   = tid >> 4;
    const int tx   = tid & 15;

    float acc[8][8];
#pragma unroll
    for (int i = 0; i < 8; i++)
#pragma unroll
        for (int j = 0; j < 8; j++) acc[i][j] = 0.f;

    const float* Aptr = A + (long)(m0 + aRow) * lda + aK;

    for (int k0 = 0; k0 < Kd; k0 += 8) {
        float4 av = *(const float4*)(Aptr + k0);
        As[aK + 0][aRow] = av.x;
        As[aK + 1][aRow] = av.y;
        As[aK + 2][aRow] = av.z;
        As[aK + 3][aRow] = av.w;
        *(float4*)&Ws[wK][wC] = *(const float4*)(W + (long)(k0 + wK) * ldw + wC);
        __syncthreads();

#pragma unroll
        for (int kk = 0; kk < 8; kk++) {
            float a[8], bq[8];
            *(float4*)(a)      = *(const float4*)&As[kk][ty * 8];
            *(float4*)(a + 4)  = *(const float4*)&As[kk][ty * 8 + 4];
            *(float4*)(bq)     = *(const float4*)&Ws[kk][tx * 8];
            *(float4*)(bq + 4) = *(const float4*)&Ws[kk][tx * 8 + 4];
#pragma unroll
            for (int i = 0; i < 8; i++)
#pragma unroll
                for (int j = 0; j < 8; j++)
                    acc[i][j] += a[i] * bq[j];
        }
        __syncthreads();
    }

#pragma unroll
    for (int i = 0; i < 8; i++) {
        const long row = m0 + ty * 8 + i;
#pragma unroll
        for (int j = 0; j < 8; j++) {
            const int col = tx * 8 + j;
            float v = acc[i][j];
            if (bias) v += bias[col];
            C[row * ldc + col] = v;
        }
    }
}

// ---------------- input attention + top-k mask + rnn_in (half out) -------------
__global__ void __launch_bounds__(128) attn_kernel(const float* __restrict__ kb,
                                                   const float* __restrict__ vb)
{
    const int b = blockIdx.x;
    const int t = threadIdx.x;
    __shared__ float sq[NRIM * 128], skx[128], skb[128];
    __shared__ float s2[12], sm[NRIM], sp0[NRIM], sp1[NRIM];

    for (int i = t; i < NRIM * 128; i += 128) sq[i] = g_q[b * NRIM * 128 + i];
    if (t < 128) { skx[t] = g_kx[b * 128 + t]; skb[t] = kb[t]; }
    __syncthreads();

    const int w = t >> 5, lane = t & 31;
    for (int d = w; d < 12; d += 4) {
        const int n = d >> 1, m = d & 1;
        const float* kv = m ? skb : skx;
        float s = 0.f;
        for (int k = lane; k < 128; k += 32) s += sq[n * 128 + k] * kv[k];
#pragma unroll
        for (int o = 16; o; o >>= 1) s += __shfl_xor_sync(0xffffffffu, s, o);
        if (!lane) s2[d] = s * (1.0f / 16.0f);
    }
    __syncthreads();

    if (t < NRIM) {
        const int n = t;
        const float sn = s2[n * 2];
        int rank = 0;
        for (int m2 = 0; m2 < NRIM; m2++) {
            const float sv = s2[m2 * 2];
            if (sv > sn || (sv == sn && m2 < n)) rank++;
        }
        const float mk = (rank < TOPK) ? 1.0f : 0.0f;
        sm[n] = mk;
        g_mask[b * NRIM + n] = mk;
        const float a0 = s2[n * 2], a1 = s2[n * 2 + 1];
        const float mx = fmaxf(a0, a1);
        const float e0 = expf(a0 - mx), e1 = expf(a1 - mx);
        const float inv = 1.0f / (e0 + e1);
        sp0[n] = e0 * inv;
        sp1[n] = e1 * inv;
    }
    __syncthreads();

    for (int v2 = t; v2 < 208; v2 += 128) {
        float v20a = 0.f, v21a = 0.f, v20b = 0.f, v21b = 0.f;
        if (v2 < 200) {
            const int v = 2 * v2;
            v20a = 0.5f * (g_vx[b * 800 + v]     + g_vx[b * 800 + 400 + v]);
            v21a = 0.5f * (vb[v]     + vb[400 + v]);
            v20b = 0.5f * (g_vx[b * 800 + v + 1] + g_vx[b * 800 + 401 + v]);
            v21b = 0.5f * (vb[v + 1] + vb[401 + v]);
        }
#pragma unroll
        for (int n = 0; n < NRIM; n++) {
            const float va = sm[n] * (sp0[n] * v20a + sp1[n] * v21a);
            const float vbv = sm[n] * (sp0[n] * v20b + sp1[n] * v21b);
            __half2 h = __floats2half2_rn(va, vbv);
            uint32_t u; memcpy(&u, &h, 4);
            g_rnnh[(b * NRIM + n) * 208 + v2] = u;
        }
    }
}

// ---------------- communication attention (reads merged ckqv, half ctx out) ----
__global__ void __launch_bounds__(128) cattn_kernel()
{
    const int b = blockIdx.x;
    const int t = threadIdx.x;
    __shared__ float sk[NRIM * 128], sq[NRIM * 128], sv[NRIM * 400];
    __shared__ float sm[NRIM], sc[144], sp[144];

    for (int i = t; i < NRIM * 128; i += 128) {
        const int n = i >> 7, k = i & 127;
        sk[i] = g_ckqv[((long)b * NRIM + n) * 768 + k];
        sq[i] = g_ckqv[((long)b * NRIM + n) * 768 + 128 + k];
    }
    for (int i = t; i < NRIM * 400; i += 128) {
        const int n = i / 400, r = i % 400;
        sv[i] = g_ckqv[((long)b * NRIM + n) * 768 + 256 + r];
    }
    if (t < NRIM) sm[t] = g_mask[b * NRIM + t];
    __syncthreads();

    for (int d = t; d < 144; d += 128) {
        const int h = d / 36, r = d % 36, n = r / 6, m = r % 6;
        float s = 0.f;
#pragma unroll
        for (int k = 0; k < CKS; k++)
            s += sq[n * 128 + h * CKS + k] * sk[m * 128 + h * CKS + k];
        sc[d] = s * 0.17677669529663687f;
    }
    __syncthreads();

    if (t < 24) {
        const int h = t / 6, n = t % 6;
        float mx = -1e30f;
        for (int m = 0; m < 6; m++) mx = fmaxf(mx, sc[h * 36 + n * 6 + m]);
        float e[6], sum = 0.f;
        for (int m = 0; m < 6; m++) { e[m] = expf(sc[h * 36 + n * 6 + m] - mx); sum += e[m]; }
        const float inv = sm[n] / sum;
        for (int m = 0; m < 6; m++) sp[h * 36 + n * 6 + m] = e[m] * inv;
    }
    __syncthreads();

    for (int idx = t; idx < NRIM * 400; idx += 128) {
        const int n = idx / 400, r = idx % 400, h = r / 100;
        float a = 0.f;
#pragma unroll
        for (int m = 0; m < 6; m++) a += sp[h * 36 + n * 6 + m] * sv[m * 400 + r];
        g_ctxh[((long)b * NRIM + n) * 416 + r] = __float2half(a);
    }
    if (t < 96) {
        const int n = t >> 4, r = 400 + (t & 15);
        g_ctxh[((long)b * NRIM + n) * 416 + r] = __float2half(0.f);
    }
}

// -------------------------------------------------------------------------------
extern "C" void kernel_launch(void* const* d_in, const int* in_sizes, int n_in,
                              void* d_out, int out_size)
{
    const float* x     = (const float*)d_in[0];
    const float* hs    = (const float*)d_in[1];
    const float* cs    = (const float*)d_in[2];
    const float* keyW  = (const float*)d_in[3];
    const float* keyb  = (const float*)d_in[4];
    const float* valW  = (const float*)d_in[5];
    const float* valb  = (const float*)d_in[6];
    const float* qW    = (const float*)d_in[7];
    const float* i2h   = (const float*)d_in[8];
    const float* h2h   = (const float*)d_in[9];
    const float* WkC   = (const float*)d_in[10];
    const float* WvC   = (const float*)d_in[11];
    const float* WqC   = (const float*)d_in[12];
    const float* WoC   = (const float*)d_in[13];
    float* out = (float*)d_out;

    float *kx, *q, *vx, *ckqv, *mask, *hnewf;
    uint32_t *xh, *hsh, *rnnh, *wh_val, *wh_pre, *wh_kqv, *wh_o;
    __half *hnewh, *ctxh;
    cudaGetSymbolAddress((void**)&kx,    g_kx);
    cudaGetSymbolAddress((void**)&q,     g_q);
    cudaGetSymbolAddress((void**)&vx,    g_vx);
    cudaGetSymbolAddress((void**)&ckqv,  g_ckqv);
    cudaGetSymbolAddress((void**)&mask,  g_mask);
    cudaGetSymbolAddress((void**)&hnewf, g_hnew);
    cudaGetSymbolAddress((void**)&xh,    g_xh);
    cudaGetSymbolAddress((void**)&hsh,   g_hsh);
    cudaGetSymbolAddress((void**)&rnnh,  g_rnnh);
    cudaGetSymbolAddress((void**)&hnewh, g_hnewh);
    cudaGetSymbolAddress((void**)&ctxh,  g_ctxh);
    cudaGetSymbolAddress((void**)&wh_val, g_wh_val);
    cudaGetSymbolAddress((void**)&wh_pre, g_wh_pre);
    cudaGetSymbolAddress((void**)&wh_kqv, g_wh_kqv);
    cudaGetSymbolAddress((void**)&wh_o,   g_wh_o);

    cudaFuncSetAttribute(gemm_fp16h<0>, cudaFuncAttributeMaxDynamicSharedMemorySize, GSM_PIPE);
    cudaFuncSetAttribute(gemm_fp16h<1>, cudaFuncAttributeMaxDynamicSharedMemorySize, GSM_PIPE);
    cudaFuncSetAttribute(gemm_fp16h<2>, cudaFuncAttributeMaxDynamicSharedMemorySize, GSM_PIPE);

    // ---- converts + weight packs ----
    const int nA = BSZ * 256, nB = BSZ * 768;
    f2h2<<<(nA + nB + 255) / 256, 256>>>((const float2*)x, xh, nA,
                                         (const float2*)hs, hsh, nB);
    pack_w<<<896, 256>>>(valW, 512, 800, 0, nullptr, 0, 0, 0,
                         wh_val, 800, 896, 512, 0);
    pack_pre<<<dim3(1344, 1, NRIM), 256>>>(i2h, h2h, wh_pre);
    pack_kqv<<<dim3(384, 1, NRIM), 256>>>(WkC, WqC, WvC, wh_kqv);
    pack_w<<<dim3(208, 1, NRIM), 256>>>(WoC, 400, 256, 400L * 256, nullptr, 0, 0, 0,
                                        wh_o, 256, 256, 416, 208L * 256);

    // 1+3) kx + q fused fp32 launch (top-k-critical path, z=0..5 q, z=6 kx)
    gemm128_fat<<<dim3(1, 64, 7), 256>>>(x, keyW, keyb, kx, hs, qW, q);
    // 2) vx = x @ value_W + value_b  (fp16, EP=0)
    gemm_fp16h<0><<<dim3(7, 64, 1), 256, GSM_PIPE>>>(xh, 256, 256, 0, xh, 256, 0,
                                                     wh_val, 896, 0, 256, valb, vx, 800, 800, 0,
                                                     nullptr, nullptr, nullptr, nullptr, nullptr, nullptr);
    // 4) input attention + top-k + rnn_in (half)
    attn_kernel<<<BSZ, 128>>>(keyb, valb);
    // 5+6+7) preact GEMM + fused LSTM epilogue (EP=1)
    gemm_fp16h<1><<<dim3(8, 64, NRIM), 256, GSM_PIPE>>>(rnnh, 208, NRIM * 208, 208,
                                                        hsh, 768, 128,
                                                        wh_pre, 1024, 336L * 1024, 336,
                                                        nullptr, nullptr, 1024, 0, 0,
                                                        cs, out, mask, hnewf, hnewh, nullptr);
    // 8) ck|cq|cv = h_new @ [Wk|Wq|Wv]  (fp16, EP=0)
    gemm_fp16h<0><<<dim3(6, 64, NRIM), 256, GSM_PIPE>>>((uint32_t*)hnewh, 128, NRIM * 128, 128,
                                                        (uint32_t*)hnewh, 128, 128,
                                                        wh_kqv, 768, 128L * 768, 128,
                                                        nullptr, ckqv, 768, NRIM * 768, 768,
                                                        nullptr, nullptr, nullptr, nullptr, nullptr, nullptr);
    // 9) communication attention -> ctx (half)
    cattn_kernel<<<BSZ, 128>>>();
    // 10+11) hcm GEMM + fused final-h epilogue (EP=2)
    gemm_fp16h<2><<<dim3(2, 64, NRIM), 256, GSM_PIPE>>>((uint32_t*)ctxh, 208, NRIM * 208, 208,
                                                        (uint32_t*)ctxh, 208, 208,
                                                        wh_o, 256, 208L * 256, 208,
                                                        nullptr, nullptr, 256, 0, 0,
                                                        nullptr, out, mask, hnewf, nullptr, hs);
}

// round 16
// speedup vs baseline: 1.6443x; 1.0206x over previous
#include <cuda_runtime.h>
#include <cuda_fp16.h>
#include <math.h>
#include <stdint.h>
#include <string.h>

#define BSZ   8192
#define DD    512
#define UNITS 256
#define NRIM  6
#define TOPK  4
#define NIH   2
#define IKS   64
#define IVS   400
#define NCH   4
#define CKS   32
#define CVS   100

#define BF (BSZ*NRIM*UNITS)
#define GSM_PIPE 56832   // 3 stages * (128*20 + 16*136) u32 * 4B; >= 64*132*4 staging

// ---------------- scratch ------------------------------------------------------
__device__ float g_kx  [BSZ*128];
__device__ float g_vx  [BSZ*800];
__device__ float g_q   [BSZ*NRIM*128];
__device__ float g_mask[BSZ*NRIM];
__device__ float g_hnew[BF];
__device__ float g_ckqv[BSZ*NRIM*768];       // [k 0:128 | q 128:256 | v 256:656 | pad]
// half A-side operands
__device__ uint32_t g_xh   [BSZ*256];
__device__ uint32_t g_hsh  [BSZ*768];
__device__ uint32_t g_rnnh [BSZ*NRIM*208];
__device__ __half   g_hnewh[BF];
__device__ __half   g_ctxh [BSZ*NRIM*416];
// packed half2 weights, layout [k/2][Npad], zero-padded
__device__ uint32_t g_wh_val[256*896];
__device__ uint32_t g_wh_pre[6*336*1024];    // gate-interleaved cols: n' = u*4+gate
__device__ uint32_t g_wh_kqv[6*128*768];
__device__ uint32_t g_wh_o  [6*208*256];

// ---------------- fp32 -> half2 convert (dual-array fat kernel) ----------------
__global__ void f2h2(const float2* __restrict__ srcA, uint32_t* __restrict__ dstA, int nA,
                     const float2* __restrict__ srcB, uint32_t* __restrict__ dstB, int nB)
{
    const long gi = (long)blockIdx.x * 256 + threadIdx.x;
    const float2* src;
    uint32_t* dst;
    long i;
    if (gi < nA) { src = srcA; dst = dstA; i = gi; }
    else { i = gi - nA; if (i >= nB) return; src = srcB; dst = dstB; }
    float2 v = src[i];
    __half2 h = __floats2half2_rn(v.x, v.y);
    uint32_t u; memcpy(&u, &h, 4);
    dst[i] = u;
}

// ---------------- weight pack --------------------------------------------------
__global__ void pack_w(const float* __restrict__ W1, int K1, int ldw1, long sW1,
                       const float* __restrict__ W2, int K2, int ldw2, long sW2,
                       uint32_t* __restrict__ Wh, int N, int Npad, int Ktot, long sWh)
{
    const int z = blockIdx.z;
    const long idx = (long)blockIdx.x * 256 + threadIdx.x;
    const int rows = Ktot / 2;
    if (idx >= (long)rows * Npad) return;
    const int k2 = (int)(idx / Npad);
    const int n  = (int)(idx % Npad);
    const int K1p = (K1 + 31) & ~31;

    float v[2];
#pragma unroll
    for (int e = 0; e < 2; e++) {
        const int k = 2 * k2 + e;
        float x = 0.f;
        if (n < N) {
            if (k < K1p) { if (k < K1) x = W1[(long)z * sW1 + (long)k * ldw1 + n]; }
            else { const int ks = k - K1p; if (ks < K2) x = W2[(long)z * sW2 + (long)ks * ldw2 + n]; }
        }
        v[e] = x;
    }
    __half2 h = __float22half2_rn(make_float2(v[0], v[1]));
    uint32_t u; memcpy(&u, &h, 4);
    Wh[(long)z * sWh + idx] = u;
}

// ---------------- preact weight pack: gate-interleaved cols --------------------
__global__ void pack_pre(const float* __restrict__ i2h, const float* __restrict__ h2h,
                         uint32_t* __restrict__ Wh)
{
    const int z = blockIdx.z;
    const int idx = blockIdx.x * 256 + threadIdx.x;    // 0..344063
    const int k2 = idx >> 10, np = idx & 1023;
    const int u = np >> 2, gte = np & 3;
    const int n = gte * 256 + u;
    float v[2];
#pragma unroll
    for (int e = 0; e < 2; e++) {
        const int k = 2 * k2 + e;
        float x = 0.f;
        if (k < 416) { if (k < 400) x = i2h[((long)z * 400 + k) * 1024 + n]; }
        else         { x = h2h[((long)z * 256 + (k - 416)) * 1024 + n]; }
        v[e] = x;
    }
    __half2 h = __float22half2_rn(make_float2(v[0], v[1]));
    uint32_t u32v; memcpy(&u32v, &h, 4);
    Wh[(long)z * (336L * 1024) + idx] = u32v;
}

// ---------------- merged comm weight pack --------------------------------------
__global__ void pack_kqv(const float* __restrict__ Wk, const float* __restrict__ Wq,
                         const float* __restrict__ Wv, uint32_t* __restrict__ Wh)
{
    const int z = blockIdx.z;
    const int idx = blockIdx.x * 256 + threadIdx.x;
    const int k2 = idx / 768, n = idx % 768;
    float v[2];
#pragma unroll
    for (int e = 0; e < 2; e++) {
        const int k = 2 * k2 + e;
        float x = 0.f;
        if (n < 128)      x = Wk[((long)z * 256 + k) * 128 + n];
        else if (n < 256) x = Wq[((long)z * 256 + k) * 128 + (n - 128)];
        else if (n < 656) x = Wv[((long)z * 256 + k) * 400 + (n - 256)];
        v[e] = x;
    }
    __half2 h = __float22half2_rn(make_float2(v[0], v[1]));
    uint32_t u; memcpy(&u, &h, 4);
    Wh[(long)z * (128L * 768) + idx] = u;
}

// =================== fp16 tensor-core GEMM (templated epilogue) ===============
__device__ __forceinline__ void mma_fp16(float* d, const uint32_t* a, const uint32_t* b) {
    asm volatile(
        "mma.sync.aligned.m16n8k16.row.col.f32.f16.f16.f32 "
        "{%0,%1,%2,%3}, {%4,%5,%6,%7}, {%8,%9}, {%0,%1,%2,%3};\n"
        : "+f"(d[0]), "+f"(d[1]), "+f"(d[2]), "+f"(d[3])
        : "r"(a[0]), "r"(a[1]), "r"(a[2]), "r"(a[3]),
          "r"(b[0]), "r"(b[1]));
}
__device__ __forceinline__ void cpa16(uint32_t dst, const void* src) {
    asm volatile("cp.async.ca.shared.global [%0], [%1], 16;\n" :: "r"(dst), "l"(src));
}
#define CP_COMMIT() asm volatile("cp.async.commit_group;\n" ::: "memory")
#define CP_WAIT1()  asm volatile("cp.async.wait_group 1;\n" ::: "memory")
#define CP_WAIT0()  asm volatile("cp.async.wait_group 0;\n" ::: "memory")

__device__ __forceinline__ float sigf(float x) { return 1.f / (1.f + expf(-x)); }

// stage layout (u32): A [128][20] at +0, W [16][136] at +2560; stage stride 4736
template <int EP>
__global__ void __launch_bounds__(256) gemm_fp16h(
    const uint32_t* __restrict__ A1, int K1u, int lda1, long sA1,
    const uint32_t* __restrict__ A2, int lda2, long sA2,
    const uint32_t* __restrict__ Wh, int ldwh, long sWh, int Ktotu,
    const float* __restrict__ bias, float* __restrict__ C, int N, int ldc, long sC,
    const float* __restrict__ cs, float* __restrict__ outp,
    const float* __restrict__ mask, float* __restrict__ hnew,
    __half* __restrict__ hnewh, const float* __restrict__ hs)
{
    extern __shared__ uint32_t sm[];

    const int tid = threadIdx.x, wid = tid >> 5, lane = tid & 31;
    const int warp_m = (wid & 1) * 64, warp_n = (wid >> 1) * 32;
    const int g = lane >> 2, qd = lane & 3;
    const int m0 = blockIdx.y * 128, n0 = blockIdx.x * 128, z = blockIdx.z;
    A1 += (long)z * sA1;
    A2 += (long)z * sA2;
    Wh += (long)z * sWh;
    if (C) C += (long)z * sC;

    const uint32_t smb = (uint32_t)__cvta_generic_to_shared(sm);
    const int aRow = tid >> 1, aC0 = tid & 1;

    auto issue = [&](int t) {
        const int buf = t % 3;
        const uint32_t sA = smb + (uint32_t)buf * 4736u * 4u;
        const uint32_t sW = sA + 2560u * 4u;
        const int ku0 = t * 16;
#pragma unroll
        for (int c = 0; c < 2; c++) {
            const int o = ku0 + (aC0 + 2 * c) * 4;
            const uint32_t* src = (o < K1u) ? A1 + (long)(m0 + aRow) * lda1 + o
                                            : A2 + (long)(m0 + aRow) * lda2 + (o - K1u);
            cpa16(sA + (uint32_t)(aRow * 20 + (aC0 + 2 * c) * 4) * 4u, src);
        }
#pragma unroll
        for (int i = 0; i < 2; i++) {
            const int idx = i * 256 + tid;
            const int r = idx >> 5, cu = (idx & 31) * 4;
            cpa16(sW + (uint32_t)(r * 136 + cu) * 4u,
                  Wh + (long)(ku0 + r) * ldwh + n0 + cu);
        }
    };

    float acc[4][4][4];
#pragma unroll
    for (int i = 0; i < 4; i++)
#pragma unroll
        for (int j = 0; j < 4; j++)
#pragma unroll
            for (int r = 0; r < 4; r++) acc[i][j][r] = 0.f;

    const int T = Ktotu / 16;
    issue(0); CP_COMMIT();
    issue(1); CP_COMMIT();

    for (int t = 0; t < T; t++) {
        CP_WAIT1();
        __syncthreads();
        if (t + 2 < T) issue(t + 2);
        CP_COMMIT();

        const uint32_t* Asb = sm + (t % 3) * 4736;
        const uint32_t* Wsb = Asb + 2560;
#pragma unroll
        for (int ks2 = 0; ks2 < 2; ks2++) {
            const int kb = ks2 * 8;
            uint32_t af[4][4], bf[4][2];
#pragma unroll
            for (int i = 0; i < 4; i++) {
                const int mb = warp_m + i * 16 + g;
                af[i][0] = Asb[mb * 20 + kb + qd];
                af[i][1] = Asb[(mb + 8) * 20 + kb + qd];
                af[i][2] = Asb[mb * 20 + kb + qd + 4];
                af[i][3] = Asb[(mb + 8) * 20 + kb + qd + 4];
            }
#pragma unroll
            for (int j = 0; j < 4; j++) {
                const int nb = warp_n + j * 8 + g;
                bf[j][0] = Wsb[(kb + qd) * 136 + nb];
                bf[j][1] = Wsb[(kb + qd + 4) * 136 + nb];
            }
#pragma unroll
            for (int i = 0; i < 4; i++)
#pragma unroll
                for (int j = 0; j < 4; j++)
                    mma_fp16(acc[i][j], af[i], bf[j]);
        }
    }

    if (EP == 0) {
#pragma unroll
        for (int i = 0; i < 4; i++) {
            const long mA = m0 + warp_m + i * 16 + g;
            const long mB = mA + 8;
#pragma unroll
            for (int j = 0; j < 4; j++) {
                const int n = n0 + warp_n + j * 8 + qd * 2;
#pragma unroll
                for (int e = 0; e < 2; e++) {
                    const int col = n + e;
                    if (col < N) {
                        float vA = acc[i][j][e];
                        float vB = acc[i][j][2 + e];
                        if (bias) { vA += bias[col]; vB += bias[col]; }
                        C[mA * ldc + col] = vA;
                        C[mB * ldc + col] = vB;
                    }
                }
            }
        }
    } else if (EP == 1) {
        // ---- LSTM epilogue, two 64-row phases ----
        CP_WAIT0();
        __syncthreads();
        float* stg = (float*)sm;        // [64][132]
#pragma unroll
        for (int ph = 0; ph < 2; ph++) {
            if (warp_m == ph * 64) {
#pragma unroll
                for (int i = 0; i < 4; i++) {
                    const int rA = i * 16 + g, rB = rA + 8;
#pragma unroll
                    for (int j = 0; j < 4; j++) {
                        const int cl = warp_n + j * 8 + qd * 2;
                        stg[rA * 132 + cl]     = acc[i][j][0];
                        stg[rA * 132 + cl + 1] = acc[i][j][1];
                        stg[rB * 132 + cl]     = acc[i][j][2];
                        stg[rB * 132 + cl + 1] = acc[i][j][3];
                    }
                }
            }
            __syncthreads();
            for (int s = tid; s < 64 * 32; s += 256) {
                const int row = ph * 64 + (s >> 5), uu = s & 31;
                float4 gt = *(const float4*)&stg[(s >> 5) * 132 + uu * 4];
                const long bn = (long)(m0 + row) * NRIM + z;
                const long i  = bn * 256 + (n0 >> 2) + uu;
                const float nc = tanhf(gt.x);
                const float ig = sigf(gt.y);
                const float fg = sigf(gt.z);
                const float og = sigf(gt.w);
                const float cold = cs[i];
                const float c = cold * fg + ig * nc;
                const float h = og * tanhf(c);
                hnew[i]  = h;
                hnewh[i] = __float2half(h);
                outp[2L * BF + i] = (mask[bn] != 0.f) ? c : cold;
            }
            __syncthreads();
        }
    } else {
        // ---- final-h epilogue ----
#pragma unroll
        for (int i = 0; i < 4; i++) {
            const long mA = m0 + warp_m + i * 16 + g;
            const long mB = mA + 8;
            const long bnA = mA * NRIM + z, bnB = mB * NRIM + z;
            const float mkA = mask[bnA], mkB = mask[bnB];
#pragma unroll
            for (int j = 0; j < 4; j++) {
                const int col = n0 + warp_n + j * 8 + qd * 2;
#pragma unroll
                for (int e = 0; e < 2; e++) {
                    const long iA = bnA * 256 + col + e;
                    const long iB = bnB * 256 + col + e;
                    const float hA = (mkA != 0.f) ? (acc[i][j][e] + hnew[iA]) : hs[iA];
                    const float hB = (mkB != 0.f) ? (acc[i][j][2 + e] + hnew[iB]) : hs[iB];
                    outp[iA] = hA; outp[BF + iA] = hA;
                    outp[iB] = hB; outp[BF + iB] = hB;
                }
            }
        }
    }
}

// =================== fp32 GEMM, fat kx+q merge (top-k path) ===================
__global__ void __launch_bounds__(256) gemm128_fat(
    const float* __restrict__ x,  const float* __restrict__ keyW,
    const float* __restrict__ keyb, float* __restrict__ kx,
    const float* __restrict__ hs, const float* __restrict__ qW,
    float* __restrict__ qout)
{
    const int z = blockIdx.z;
    const float* A; const float* W; const float* bias; float* C;
    int Kd, lda, ldw, ldc;
    if (z < 6) {
        A = hs + z * UNITS; W = qW + (long)z * 256 * 128; bias = nullptr;
        C = qout + z * 128; Kd = 256; lda = NRIM * UNITS; ldw = 128; ldc = NRIM * 128;
    } else {
        A = x; W = keyW; bias = keyb; C = kx;
        Kd = 512; lda = 512; ldw = 128; ldc = 128;
    }

    __shared__ float As[8][128];
    __shared__ float Ws[8][128];

    const int tid = threadIdx.x;
    const int m0  = blockIdx.y * 128;

    const int aRow = tid >> 1;
    const int aK   = (tid & 1) * 4;
    const int wK   = tid >> 5;
    const int wC   = (tid & 31) * 4;
    const int ty   = tid >> 4;
    const int tx   = tid & 15;

    float acc[8][8];
#pragma unroll
    for (int i = 0; i < 8; i++)
#pragma unroll
        for (int j = 0; j < 8; j++) acc[i][j] = 0.f;

    const float* Aptr = A + (long)(m0 + aRow) * lda + aK;

    for (int k0 = 0; k0 < Kd; k0 += 8) {
        float4 av = *(const float4*)(Aptr + k0);
        As[aK + 0][aRow] = av.x;
        As[aK + 1][aRow] = av.y;
        As[aK + 2][aRow] = av.z;
        As[aK + 3][aRow] = av.w;
        *(float4*)&Ws[wK][wC] = *(const float4*)(W + (long)(k0 + wK) * ldw + wC);
        __syncthreads();

#pragma unroll
        for (int kk = 0; kk < 8; kk++) {
            float a[8], bq[8];
            *(float4*)(a)      = *(const float4*)&As[kk][ty * 8];
            *(float4*)(a + 4)  = *(const float4*)&As[kk][ty * 8 + 4];
            *(float4*)(bq)     = *(const float4*)&Ws[kk][tx * 8];
            *(float4*)(bq + 4) = *(const float4*)&Ws[kk][tx * 8 + 4];
#pragma unroll
            for (int i = 0; i < 8; i++)
#pragma unroll
                for (int j = 0; j < 8; j++)
                    acc[i][j] += a[i] * bq[j];
        }
        __syncthreads();
    }

#pragma unroll
    for (int i = 0; i < 8; i++) {
        const long row = m0 + ty * 8 + i;
#pragma unroll
        for (int j = 0; j < 8; j++) {
            const int col = tx * 8 + j;
            float v = acc[i][j];
            if (bias) v += bias[col];
            C[row * ldc + col] = v;
        }
    }
}

// ---------------- input attention + top-k mask + rnn_in (half out) -------------
__global__ void __launch_bounds__(128) attn_kernel(const float* __restrict__ kb,
                                                   const float* __restrict__ vb)
{
    const int b = blockIdx.x;
    const int t = threadIdx.x;
    __shared__ float sq[NRIM * 128], skx[128], skb[128];
    __shared__ float s2[12], sm[NRIM], sp0[NRIM], sp1[NRIM];

    for (int i = t; i < NRIM * 128; i += 128) sq[i] = g_q[b * NRIM * 128 + i];
    if (t < 128) { skx[t] = g_kx[b * 128 + t]; skb[t] = kb[t]; }
    __syncthreads();

    const int w = t >> 5, lane = t & 31;
    for (int d = w; d < 12; d += 4) {
        const int n = d >> 1, m = d & 1;
        const float* kv = m ? skb : skx;
        float s = 0.f;
        for (int k = lane; k < 128; k += 32) s += sq[n * 128 + k] * kv[k];
#pragma unroll
        for (int o = 16; o; o >>= 1) s += __shfl_xor_sync(0xffffffffu, s, o);
        if (!lane) s2[d] = s * (1.0f / 16.0f);
    }
    __syncthreads();

    if (t < NRIM) {
        const int n = t;
        const float sn = s2[n * 2];
        int rank = 0;
        for (int m2 = 0; m2 < NRIM; m2++) {
            const float sv = s2[m2 * 2];
            if (sv > sn || (sv == sn && m2 < n)) rank++;
        }
        const float mk = (rank < TOPK) ? 1.0f : 0.0f;
        sm[n] = mk;
        g_mask[b * NRIM + n] = mk;
        const float a0 = s2[n * 2], a1 = s2[n * 2 + 1];
        const float mx = fmaxf(a0, a1);
        const float e0 = expf(a0 - mx), e1 = expf(a1 - mx);
        const float inv = 1.0f / (e0 + e1);
        sp0[n] = e0 * inv;
        sp1[n] = e1 * inv;
    }
    __syncthreads();

    for (int v2 = t; v2 < 208; v2 += 128) {
        float v20a = 0.f, v21a = 0.f, v20b = 0.f, v21b = 0.f;
        if (v2 < 200) {
            const int v = 2 * v2;
            v20a = 0.5f * (g_vx[b * 800 + v]     + g_vx[b * 800 + 400 + v]);
            v21a = 0.5f * (vb[v]     + vb[400 + v]);
            v20b = 0.5f * (g_vx[b * 800 + v + 1] + g_vx[b * 800 + 401 + v]);
            v21b = 0.5f * (vb[v + 1] + vb[401 + v]);
        }
#pragma unroll
        for (int n = 0; n < NRIM; n++) {
            const float va = sm[n] * (sp0[n] * v20a + sp1[n] * v21a);
            const float vbv = sm[n] * (sp0[n] * v20b + sp1[n] * v21b);
            __half2 h = __floats2half2_rn(va, vbv);
            uint32_t u; memcpy(&u, &h, 4);
            g_rnnh[(b * NRIM + n) * 208 + v2] = u;
        }
    }
}

// ---------------- communication attention (reads merged ckqv, half ctx out) ----
__global__ void __launch_bounds__(128) cattn_kernel()
{
    const int b = blockIdx.x;
    const int t = threadIdx.x;
    __shared__ float sk[NRIM * 128], sq[NRIM * 128], sv[NRIM * 400];
    __shared__ float sm[NRIM], sc[144], sp[144];

    for (int i = t; i < NRIM * 128; i += 128) {
        const int n = i >> 7, k = i & 127;
        sk[i] = g_ckqv[((long)b * NRIM + n) * 768 + k];
        sq[i] = g_ckqv[((long)b * NRIM + n) * 768 + 128 + k];
    }
    for (int i = t; i < NRIM * 400; i += 128) {
        const int n = i / 400, r = i % 400;
        sv[i] = g_ckqv[((long)b * NRIM + n) * 768 + 256 + r];
    }
    if (t < NRIM) sm[t] = g_mask[b * NRIM + t];
    __syncthreads();

    for (int d = t; d < 144; d += 128) {
        const int h = d / 36, r = d % 36, n = r / 6, m = r % 6;
        float s = 0.f;
#pragma unroll
        for (int k = 0; k < CKS; k++)
            s += sq[n * 128 + h * CKS + k] * sk[m * 128 + h * CKS + k];
        sc[d] = s * 0.17677669529663687f;
    }
    __syncthreads();

    if (t < 24) {
        const int h = t / 6, n = t % 6;
        float mx = -1e30f;
        for (int m = 0; m < 6; m++) mx = fmaxf(mx, sc[h * 36 + n * 6 + m]);
        float e[6], sum = 0.f;
        for (int m = 0; m < 6; m++) { e[m] = expf(sc[h * 36 + n * 6 + m] - mx); sum += e[m]; }
        const float inv = sm[n] / sum;
        for (int m = 0; m < 6; m++) sp[h * 36 + n * 6 + m] = e[m] * inv;
    }
    __syncthreads();

    for (int idx = t; idx < NRIM * 400; idx += 128) {
        const int n = idx / 400, r = idx % 400, h = r / 100;
        float a = 0.f;
#pragma unroll
        for (int m = 0; m < 6; m++) a += sp[h * 36 + n * 6 + m] * sv[m * 400 + r];
        g_ctxh[((long)b * NRIM + n) * 416 + r] = __float2half(a);
    }
    if (t < 96) {
        const int n = t >> 4, r = 400 + (t & 15);
        g_ctxh[((long)b * NRIM + n) * 416 + r] = __float2half(0.f);
    }
}

// -------------------------------------------------------------------------------
extern "C" void kernel_launch(void* const* d_in, const int* in_sizes, int n_in,
                              void* d_out, int out_size)
{
    const float* x     = (const float*)d_in[0];
    const float* hs    = (const float*)d_in[1];
    const float* cs    = (const float*)d_in[2];
    const float* keyW  = (const float*)d_in[3];
    const float* keyb  = (const float*)d_in[4];
    const float* valW  = (const float*)d_in[5];
    const float* valb  = (const float*)d_in[6];
    const float* qW    = (const float*)d_in[7];
    const float* i2h   = (const float*)d_in[8];
    const float* h2h   = (const float*)d_in[9];
    const float* WkC   = (const float*)d_in[10];
    const float* WvC   = (const float*)d_in[11];
    const float* WqC   = (const float*)d_in[12];
    const float* WoC   = (const float*)d_in[13];
    float* out = (float*)d_out;

    float *kx, *q, *vx, *ckqv, *mask, *hnewf;
    uint32_t *xh, *hsh, *rnnh, *wh_val, *wh_pre, *wh_kqv, *wh_o;
    __half *hnewh, *ctxh;
    cudaGetSymbolAddress((void**)&kx,    g_kx);
    cudaGetSymbolAddress((void**)&q,     g_q);
    cudaGetSymbolAddress((void**)&vx,    g_vx);
    cudaGetSymbolAddress((void**)&ckqv,  g_ckqv);
    cudaGetSymbolAddress((void**)&mask,  g_mask);
    cudaGetSymbolAddress((void**)&hnewf, g_hnew);
    cudaGetSymbolAddress((void**)&xh,    g_xh);
    cudaGetSymbolAddress((void**)&hsh,   g_hsh);
    cudaGetSymbolAddress((void**)&rnnh,  g_rnnh);
    cudaGetSymbolAddress((void**)&hnewh, g_hnewh);
    cudaGetSymbolAddress((void**)&ctxh,  g_ctxh);
    cudaGetSymbolAddress((void**)&wh_val, g_wh_val);
    cudaGetSymbolAddress((void**)&wh_pre, g_wh_pre);
    cudaGetSymbolAddress((void**)&wh_kqv, g_wh_kqv);
    cudaGetSymbolAddress((void**)&wh_o,   g_wh_o);

    cudaFuncSetAttribute(gemm_fp16h<0>, cudaFuncAttributeMaxDynamicSharedMemorySize, GSM_PIPE);
    cudaFuncSetAttribute(gemm_fp16h<1>, cudaFuncAttributeMaxDynamicSharedMemorySize, GSM_PIPE);
    cudaFuncSetAttribute(gemm_fp16h<2>, cudaFuncAttributeMaxDynamicSharedMemorySize, GSM_PIPE);

    // ---- fork a second graph branch for the independent fp32 kx+q GEMM ----
    cudaStream_t s2;
    cudaEvent_t eF, eJ;
    cudaStreamCreateWithFlags(&s2, cudaStreamNonBlocking);
    cudaEventCreateWithFlags(&eF, cudaEventDisableTiming);
    cudaEventCreateWithFlags(&eJ, cudaEventDisableTiming);

    cudaEventRecord(eF, 0);
    cudaStreamWaitEvent(s2, eF, 0);
    // Branch B (s2): 1+3) kx + q fused fp32 launch (reads raw inputs only)
    gemm128_fat<<<dim3(1, 64, 7), 256, 0, s2>>>(x, keyW, keyb, kx, hs, qW, q);

    // Branch A (origin stream): converts + packs + vx
    const int nA = BSZ * 256, nB = BSZ * 768;
    f2h2<<<(nA + nB + 255) / 256, 256>>>((const float2*)x, xh, nA,
                                         (const float2*)hs, hsh, nB);
    pack_w<<<896, 256>>>(valW, 512, 800, 0, nullptr, 0, 0, 0,
                         wh_val, 800, 896, 512, 0);
    // 2) vx = x @ value_W + value_b  (fp16, EP=0)
    gemm_fp16h<0><<<dim3(7, 64, 1), 256, GSM_PIPE>>>(xh, 256, 256, 0, xh, 256, 0,
                                                     wh_val, 896, 0, 256, valb, vx, 800, 800, 0,
                                                     nullptr, nullptr, nullptr, nullptr, nullptr, nullptr);
    pack_pre<<<dim3(1344, 1, NRIM), 256>>>(i2h, h2h, wh_pre);
    pack_kqv<<<dim3(384, 1, NRIM), 256>>>(WkC, WqC, WvC, wh_kqv);
    pack_w<<<dim3(208, 1, NRIM), 256>>>(WoC, 400, 256, 400L * 256, nullptr, 0, 0, 0,
                                        wh_o, 256, 256, 416, 208L * 256);

    // ---- join branch B before attention (needs kx, q) ----
    cudaEventRecord(eJ, s2);
    cudaStreamWaitEvent(0, eJ, 0);

    // 4) input attention + top-k + rnn_in (half)
    attn_kernel<<<BSZ, 128>>>(keyb, valb);
    // 5+6+7) preact GEMM + fused LSTM epilogue (EP=1)
    gemm_fp16h<1><<<dim3(8, 64, NRIM), 256, GSM_PIPE>>>(rnnh, 208, NRIM * 208, 208,
                                                        hsh, 768, 128,
                                                        wh_pre, 1024, 336L * 1024, 336,
                                                        nullptr, nullptr, 1024, 0, 0,
                                                        cs, out, mask, hnewf, hnewh, nullptr);
    // 8) ck|cq|cv = h_new @ [Wk|Wq|Wv]  (fp16, EP=0)
    gemm_fp16h<0><<<dim3(6, 64, NRIM), 256, GSM_PIPE>>>((uint32_t*)hnewh, 128, NRIM * 128, 128,
                                                        (uint32_t*)hnewh, 128, 128,
                                                        wh_kqv, 768, 128L * 768, 128,
                                                        nullptr, ckqv, 768, NRIM * 768, 768,
                                                        nullptr, nullptr, nullptr, nullptr, nullptr, nullptr);
    // 9) communication attention -> ctx (half)
    cattn_kernel<<<BSZ, 128>>>();
    // 10+11) hcm GEMM + fused final-h epilogue (EP=2)
    gemm_fp16h<2><<<dim3(2, 64, NRIM), 256, GSM_PIPE>>>((uint32_t*)ctxh, 208, NRIM * 208, 208,
                                                        (uint32_t*)ctxh, 208, 208,
                                                        wh_o, 256, 208L * 256, 208,
                                                        nullptr, nullptr, 256, 0, 0,
                                                        nullptr, out, mask, hnewf, nullptr, hs);
    // NOTE: s2/eF/eJ intentionally not destroyed here — destroying resources that
    // participate in an active stream capture is illegal; handles are few (one set
    // per non-replay invocation) and graph replays never re-enter this function.
}

// round 17
// speedup vs baseline: 1.6823x; 1.0231x over previous
#include <cuda_runtime.h>
#include <cuda_fp16.h>
#include <math.h>
#include <stdint.h>
#include <string.h>

#define BSZ   8192
#define DD    512
#define UNITS 256
#define NRIM  6
#define TOPK  4
#define NIH   2
#define IKS   64
#define IVS   400
#define NCH   4
#define CKS   32
#define CVS   100

#define BF (BSZ*NRIM*UNITS)
#define GSM_PIPE 56832   // 3 stages * (128*20 + 16*136) u32 * 4B; >= 64*132*4 staging

// ---------------- scratch ------------------------------------------------------
__device__ float g_kx  [BSZ*128];
__device__ float g_vx  [BSZ*800];
__device__ float g_q   [BSZ*NRIM*128];
__device__ float g_mask[BSZ*NRIM];
__device__ float g_hnew[BF];
__device__ float g_ckqv[BSZ*NRIM*768];       // [k 0:128 | q 128:256 | v 256:656 | pad]
// half A-side operands
__device__ uint32_t g_xh   [BSZ*256];
__device__ uint32_t g_hsh  [BSZ*768];
__device__ uint32_t g_rnnh [BSZ*NRIM*208];
__device__ __half   g_hnewh[BF];
__device__ __half   g_ctxh [BSZ*NRIM*416];
// packed half2 weights, layout [k/2][Npad], zero-padded
__device__ uint32_t g_wh_val[256*896];
__device__ uint32_t g_wh_pre[6*336*1024];    // gate-interleaved cols: n' = u*4+gate
__device__ uint32_t g_wh_kqv[6*128*768];
__device__ uint32_t g_wh_o  [6*208*256];

// ---------------- fp32 -> half2 convert (dual-array fat kernel) ----------------
__global__ void f2h2(const float2* __restrict__ srcA, uint32_t* __restrict__ dstA, int nA,
                     const float2* __restrict__ srcB, uint32_t* __restrict__ dstB, int nB)
{
    const long gi = (long)blockIdx.x * 256 + threadIdx.x;
    const float2* src;
    uint32_t* dst;
    long i;
    if (gi < nA) { src = srcA; dst = dstA; i = gi; }
    else { i = gi - nA; if (i >= nB) return; src = srcB; dst = dstB; }
    float2 v = src[i];
    __half2 h = __floats2half2_rn(v.x, v.y);
    uint32_t u; memcpy(&u, &h, 4);
    dst[i] = u;
}

// ---------------- weight pack --------------------------------------------------
__global__ void pack_w(const float* __restrict__ W1, int K1, int ldw1, long sW1,
                       const float* __restrict__ W2, int K2, int ldw2, long sW2,
                       uint32_t* __restrict__ Wh, int N, int Npad, int Ktot, long sWh)
{
    const int z = blockIdx.z;
    const long idx = (long)blockIdx.x * 256 + threadIdx.x;
    const int rows = Ktot / 2;
    if (idx >= (long)rows * Npad) return;
    const int k2 = (int)(idx / Npad);
    const int n  = (int)(idx % Npad);
    const int K1p = (K1 + 31) & ~31;

    float v[2];
#pragma unroll
    for (int e = 0; e < 2; e++) {
        const int k = 2 * k2 + e;
        float x = 0.f;
        if (n < N) {
            if (k < K1p) { if (k < K1) x = W1[(long)z * sW1 + (long)k * ldw1 + n]; }
            else { const int ks = k - K1p; if (ks < K2) x = W2[(long)z * sW2 + (long)ks * ldw2 + n]; }
        }
        v[e] = x;
    }
    __half2 h = __float22half2_rn(make_float2(v[0], v[1]));
    uint32_t u; memcpy(&u, &h, 4);
    Wh[(long)z * sWh + idx] = u;
}

// ---------------- preact weight pack: gate-interleaved cols --------------------
__global__ void pack_pre(const float* __restrict__ i2h, const float* __restrict__ h2h,
                         uint32_t* __restrict__ Wh)
{
    const int z = blockIdx.z;
    const int idx = blockIdx.x * 256 + threadIdx.x;    // 0..344063
    const int k2 = idx >> 10, np = idx & 1023;
    const int u = np >> 2, gte = np & 3;
    const int n = gte * 256 + u;
    float v[2];
#pragma unroll
    for (int e = 0; e < 2; e++) {
        const int k = 2 * k2 + e;
        float x = 0.f;
        if (k < 416) { if (k < 400) x = i2h[((long)z * 400 + k) * 1024 + n]; }
        else         { x = h2h[((long)z * 256 + (k - 416)) * 1024 + n]; }
        v[e] = x;
    }
    __half2 h = __float22half2_rn(make_float2(v[0], v[1]));
    uint32_t u32v; memcpy(&u32v, &h, 4);
    Wh[(long)z * (336L * 1024) + idx] = u32v;
}

// ---------------- merged comm weight pack --------------------------------------
__global__ void pack_kqv(const float* __restrict__ Wk, const float* __restrict__ Wq,
                         const float* __restrict__ Wv, uint32_t* __restrict__ Wh)
{
    const int z = blockIdx.z;
    const int idx = blockIdx.x * 256 + threadIdx.x;
    const int k2 = idx / 768, n = idx % 768;
    float v[2];
#pragma unroll
    for (int e = 0; e < 2; e++) {
        const int k = 2 * k2 + e;
        float x = 0.f;
        if (n < 128)      x = Wk[((long)z * 256 + k) * 128 + n];
        else if (n < 256) x = Wq[((long)z * 256 + k) * 128 + (n - 128)];
        else if (n < 656) x = Wv[((long)z * 256 + k) * 400 + (n - 256)];
        v[e] = x;
    }
    __half2 h = __float22half2_rn(make_float2(v[0], v[1]));
    uint32_t u; memcpy(&u, &h, 4);
    Wh[(long)z * (128L * 768) + idx] = u;
}

// =================== fp16 tensor-core GEMM (templated epilogue) ===============
__device__ __forceinline__ void mma_fp16(float* d, const uint32_t* a, const uint32_t* b) {
    asm volatile(
        "mma.sync.aligned.m16n8k16.row.col.f32.f16.f16.f32 "
        "{%0,%1,%2,%3}, {%4,%5,%6,%7}, {%8,%9}, {%0,%1,%2,%3};\n"
        : "+f"(d[0]), "+f"(d[1]), "+f"(d[2]), "+f"(d[3])
        : "r"(a[0]), "r"(a[1]), "r"(a[2]), "r"(a[3]),
          "r"(b[0]), "r"(b[1]));
}
__device__ __forceinline__ void cpa16(uint32_t dst, const void* src) {
    asm volatile("cp.async.ca.shared.global [%0], [%1], 16;\n" :: "r"(dst), "l"(src));
}
#define CP_COMMIT() asm volatile("cp.async.commit_group;\n" ::: "memory")
#define CP_WAIT1()  asm volatile("cp.async.wait_group 1;\n" ::: "memory")
#define CP_WAIT0()  asm volatile("cp.async.wait_group 0;\n" ::: "memory")

__device__ __forceinline__ float sigf(float x) { return 1.f / (1.f + expf(-x)); }

// stage layout (u32): A [128][20] at +0, W [16][136] at +2560; stage stride 4736
template <int EP>
__global__ void __launch_bounds__(256) gemm_fp16h(
    const uint32_t* __restrict__ A1, int K1u, int lda1, long sA1,
    const uint32_t* __restrict__ A2, int lda2, long sA2,
    const uint32_t* __restrict__ Wh, int ldwh, long sWh, int Ktotu,
    const float* __restrict__ bias, float* __restrict__ C, int N, int ldc, long sC,
    const float* __restrict__ cs, float* __restrict__ outp,
    const float* __restrict__ mask, float* __restrict__ hnew,
    __half* __restrict__ hnewh, const float* __restrict__ hs)
{
    extern __shared__ uint32_t sm[];

    const int tid = threadIdx.x, wid = tid >> 5, lane = tid & 31;
    const int warp_m = (wid & 1) * 64, warp_n = (wid >> 1) * 32;
    const int g = lane >> 2, qd = lane & 3;
    const int m0 = blockIdx.y * 128, n0 = blockIdx.x * 128, z = blockIdx.z;
    A1 += (long)z * sA1;
    A2 += (long)z * sA2;
    Wh += (long)z * sWh;
    if (C) C += (long)z * sC;

    const uint32_t smb = (uint32_t)__cvta_generic_to_shared(sm);
    const int aRow = tid >> 1, aC0 = tid & 1;

    auto issue = [&](int t) {
        const int buf = t % 3;
        const uint32_t sA = smb + (uint32_t)buf * 4736u * 4u;
        const uint32_t sW = sA + 2560u * 4u;
        const int ku0 = t * 16;
#pragma unroll
        for (int c = 0; c < 2; c++) {
            const int o = ku0 + (aC0 + 2 * c) * 4;
            const uint32_t* src = (o < K1u) ? A1 + (long)(m0 + aRow) * lda1 + o
                                            : A2 + (long)(m0 + aRow) * lda2 + (o - K1u);
            cpa16(sA + (uint32_t)(aRow * 20 + (aC0 + 2 * c) * 4) * 4u, src);
        }
#pragma unroll
        for (int i = 0; i < 2; i++) {
            const int idx = i * 256 + tid;
            const int r = idx >> 5, cu = (idx & 31) * 4;
            cpa16(sW + (uint32_t)(r * 136 + cu) * 4u,
                  Wh + (long)(ku0 + r) * ldwh + n0 + cu);
        }
    };

    float acc[4][4][4];
#pragma unroll
    for (int i = 0; i < 4; i++)
#pragma unroll
        for (int j = 0; j < 4; j++)
#pragma unroll
            for (int r = 0; r < 4; r++) acc[i][j][r] = 0.f;

    const int T = Ktotu / 16;
    issue(0); CP_COMMIT();
    issue(1); CP_COMMIT();

    for (int t = 0; t < T; t++) {
        CP_WAIT1();
        __syncthreads();
        if (t + 2 < T) issue(t + 2);
        CP_COMMIT();

        const uint32_t* Asb = sm + (t % 3) * 4736;
        const uint32_t* Wsb = Asb + 2560;
#pragma unroll
        for (int ks2 = 0; ks2 < 2; ks2++) {
            const int kb = ks2 * 8;
            uint32_t af[4][4], bf[4][2];
#pragma unroll
            for (int i = 0; i < 4; i++) {
                const int mb = warp_m + i * 16 + g;
                af[i][0] = Asb[mb * 20 + kb + qd];
                af[i][1] = Asb[(mb + 8) * 20 + kb + qd];
                af[i][2] = Asb[mb * 20 + kb + qd + 4];
                af[i][3] = Asb[(mb + 8) * 20 + kb + qd + 4];
            }
#pragma unroll
            for (int j = 0; j < 4; j++) {
                const int nb = warp_n + j * 8 + g;
                bf[j][0] = Wsb[(kb + qd) * 136 + nb];
                bf[j][1] = Wsb[(kb + qd + 4) * 136 + nb];
            }
#pragma unroll
            for (int i = 0; i < 4; i++)
#pragma unroll
                for (int j = 0; j < 4; j++)
                    mma_fp16(acc[i][j], af[i], bf[j]);
        }
    }

    if (EP == 0) {
#pragma unroll
        for (int i = 0; i < 4; i++) {
            const long mA = m0 + warp_m + i * 16 + g;
            const long mB = mA + 8;
#pragma unroll
            for (int j = 0; j < 4; j++) {
                const int n = n0 + warp_n + j * 8 + qd * 2;
#pragma unroll
                for (int e = 0; e < 2; e++) {
                    const int col = n + e;
                    if (col < N) {
                        float vA = acc[i][j][e];
                        float vB = acc[i][j][2 + e];
                        if (bias) { vA += bias[col]; vB += bias[col]; }
                        C[mA * ldc + col] = vA;
                        C[mB * ldc + col] = vB;
                    }
                }
            }
        }
    } else if (EP == 1) {
        // ---- LSTM epilogue, two 64-row phases ----
        CP_WAIT0();
        __syncthreads();
        float* stg = (float*)sm;        // [64][132]
#pragma unroll
        for (int ph = 0; ph < 2; ph++) {
            if (warp_m == ph * 64) {
#pragma unroll
                for (int i = 0; i < 4; i++) {
                    const int rA = i * 16 + g, rB = rA + 8;
#pragma unroll
                    for (int j = 0; j < 4; j++) {
                        const int cl = warp_n + j * 8 + qd * 2;
                        stg[rA * 132 + cl]     = acc[i][j][0];
                        stg[rA * 132 + cl + 1] = acc[i][j][1];
                        stg[rB * 132 + cl]     = acc[i][j][2];
                        stg[rB * 132 + cl + 1] = acc[i][j][3];
                    }
                }
            }
            __syncthreads();
            for (int s = tid; s < 64 * 32; s += 256) {
                const int row = ph * 64 + (s >> 5), uu = s & 31;
                float4 gt = *(const float4*)&stg[(s >> 5) * 132 + uu * 4];
                const long bn = (long)(m0 + row) * NRIM + z;
                const long i  = bn * 256 + (n0 >> 2) + uu;
                const float nc = tanhf(gt.x);
                const float ig = sigf(gt.y);
                const float fg = sigf(gt.z);
                const float og = sigf(gt.w);
                const float cold = cs[i];
                const float c = cold * fg + ig * nc;
                const float h = og * tanhf(c);
                hnew[i]  = h;
                hnewh[i] = __float2half(h);
                outp[2L * BF + i] = (mask[bn] != 0.f) ? c : cold;
            }
            __syncthreads();
        }
    } else {
        // ---- final-h epilogue ----
#pragma unroll
        for (int i = 0; i < 4; i++) {
            const long mA = m0 + warp_m + i * 16 + g;
            const long mB = mA + 8;
            const long bnA = mA * NRIM + z, bnB = mB * NRIM + z;
            const float mkA = mask[bnA], mkB = mask[bnB];
#pragma unroll
            for (int j = 0; j < 4; j++) {
                const int col = n0 + warp_n + j * 8 + qd * 2;
#pragma unroll
                for (int e = 0; e < 2; e++) {
                    const long iA = bnA * 256 + col + e;
                    const long iB = bnB * 256 + col + e;
                    const float hA = (mkA != 0.f) ? (acc[i][j][e] + hnew[iA]) : hs[iA];
                    const float hB = (mkB != 0.f) ? (acc[i][j][2 + e] + hnew[iB]) : hs[iB];
                    outp[iA] = hA; outp[BF + iA] = hA;
                    outp[iB] = hB; outp[BF + iB] = hB;
                }
            }
        }
    }
}

// =================== fp32 GEMM, fat kx+q merge (top-k path) ===================
__global__ void __launch_bounds__(256) gemm128_fat(
    const float* __restrict__ x,  const float* __restrict__ keyW,
    const float* __restrict__ keyb, float* __restrict__ kx,
    const float* __restrict__ hs, const float* __restrict__ qW,
    float* __restrict__ qout)
{
    const int z = blockIdx.z;
    const float* A; const float* W; const float* bias; float* C;
    int Kd, lda, ldw, ldc;
    if (z < 6) {
        A = hs + z * UNITS; W = qW + (long)z * 256 * 128; bias = nullptr;
        C = qout + z * 128; Kd = 256; lda = NRIM * UNITS; ldw = 128; ldc = NRIM * 128;
    } else {
        A = x; W = keyW; bias = keyb; C = kx;
        Kd = 512; lda = 512; ldw = 128; ldc = 128;
    }

    __shared__ float As[8][128];
    __shared__ float Ws[8][128];

    const int tid = threadIdx.x;
    const int m0  = blockIdx.y * 128;

    const int aRow = tid >> 1;
    const int aK   = (tid & 1) * 4;
    const int wK   = tid >> 5;
    const int wC   = (tid & 31) * 4;
    const int ty   = tid >> 4;
    const int tx   = tid & 15;

    float acc[8][8];
#pragma unroll
    for (int i = 0; i < 8; i++)
#pragma unroll
        for (int j = 0; j < 8; j++) acc[i][j] = 0.f;

    const float* Aptr = A + (long)(m0 + aRow) * lda + aK;

    for (int k0 = 0; k0 < Kd; k0 += 8) {
        float4 av = *(const float4*)(Aptr + k0);
        As[aK + 0][aRow] = av.x;
        As[aK + 1][aRow] = av.y;
        As[aK + 2][aRow] = av.z;
        As[aK + 3][aRow] = av.w;
        *(float4*)&Ws[wK][wC] = *(const float4*)(W + (long)(k0 + wK) * ldw + wC);
        __syncthreads();

#pragma unroll
        for (int kk = 0; kk < 8; kk++) {
            float a[8], bq[8];
            *(float4*)(a)      = *(const float4*)&As[kk][ty * 8];
            *(float4*)(a + 4)  = *(const float4*)&As[kk][ty * 8 + 4];
            *(float4*)(bq)     = *(const float4*)&Ws[kk][tx * 8];
            *(float4*)(bq + 4) = *(const float4*)&Ws[kk][tx * 8 + 4];
#pragma unroll
            for (int i = 0; i < 8; i++)
#pragma unroll
                for (int j = 0; j < 8; j++)
                    acc[i][j] += a[i] * bq[j];
        }
        __syncthreads();
    }

#pragma unroll
    for (int i = 0; i < 8; i++) {
        const long row = m0 + ty * 8 + i;
#pragma unroll
        for (int j = 0; j < 8; j++) {
            const int col = tx * 8 + j;
            float v = acc[i][j];
            if (bias) v += bias[col];
            C[row * ldc + col] = v;
        }
    }
}

// ---------------- input attention + top-k mask + rnn_in (256 thr) --------------
__global__ void __launch_bounds__(256) attn_kernel(const float* __restrict__ kb,
                                                   const float* __restrict__ vb)
{
    const int b = blockIdx.x;
    const int t = threadIdx.x;
    __shared__ float sq[NRIM * 128], skx[128], skb[128];
    __shared__ float s2[12], sm[NRIM], sp0[NRIM], sp1[NRIM];

    for (int i = t; i < NRIM * 128; i += 256) sq[i] = g_q[b * NRIM * 128 + i];
    if (t < 128) skx[t] = g_kx[b * 128 + t];
    else skb[t - 128] = kb[t - 128];
    __syncthreads();

    const int w = t >> 5, lane = t & 31;
    for (int d = w; d < 12; d += 8) {
        const int n = d >> 1, m = d & 1;
        const float* kv = m ? skb : skx;
        float s = 0.f;
        for (int k = lane; k < 128; k += 32) s += sq[n * 128 + k] * kv[k];
#pragma unroll
        for (int o = 16; o; o >>= 1) s += __shfl_xor_sync(0xffffffffu, s, o);
        if (!lane) s2[d] = s * (1.0f / 16.0f);
    }
    __syncthreads();

    if (t < NRIM) {
        const int n = t;
        const float sn = s2[n * 2];
        int rank = 0;
        for (int m2 = 0; m2 < NRIM; m2++) {
            const float sv = s2[m2 * 2];
            if (sv > sn || (sv == sn && m2 < n)) rank++;
        }
        const float mk = (rank < TOPK) ? 1.0f : 0.0f;
        sm[n] = mk;
        g_mask[b * NRIM + n] = mk;
        const float a0 = s2[n * 2], a1 = s2[n * 2 + 1];
        const float mx = fmaxf(a0, a1);
        const float e0 = expf(a0 - mx), e1 = expf(a1 - mx);
        const float inv = 1.0f / (e0 + e1);
        sp0[n] = e0 * inv;
        sp1[n] = e1 * inv;
    }
    __syncthreads();

    for (int v2 = t; v2 < 208; v2 += 256) {
        float v20a = 0.f, v21a = 0.f, v20b = 0.f, v21b = 0.f;
        if (v2 < 200) {
            const int v = 2 * v2;
            v20a = 0.5f * (g_vx[b * 800 + v]     + g_vx[b * 800 + 400 + v]);
            v21a = 0.5f * (vb[v]     + vb[400 + v]);
            v20b = 0.5f * (g_vx[b * 800 + v + 1] + g_vx[b * 800 + 401 + v]);
            v21b = 0.5f * (vb[v + 1] + vb[401 + v]);
        }
#pragma unroll
        for (int n = 0; n < NRIM; n++) {
            const float va = sm[n] * (sp0[n] * v20a + sp1[n] * v21a);
            const float vbv = sm[n] * (sp0[n] * v20b + sp1[n] * v21b);
            __half2 h = __floats2half2_rn(va, vbv);
            uint32_t u; memcpy(&u, &h, 4);
            g_rnnh[(b * NRIM + n) * 208 + v2] = u;
        }
    }
}

// ---------------- communication attention (256 thr) ----------------------------
__global__ void __launch_bounds__(256) cattn_kernel()
{
    const int b = blockIdx.x;
    const int t = threadIdx.x;
    __shared__ float sk[NRIM * 128], sq[NRIM * 128], sv[NRIM * 400];
    __shared__ float sm[NRIM], sc[144], sp[144];

    for (int i = t; i < NRIM * 128; i += 256) {
        const int n = i >> 7, k = i & 127;
        sk[i] = g_ckqv[((long)b * NRIM + n) * 768 + k];
        sq[i] = g_ckqv[((long)b * NRIM + n) * 768 + 128 + k];
    }
    for (int i = t; i < NRIM * 400; i += 256) {
        const int n = i / 400, r = i % 400;
        sv[i] = g_ckqv[((long)b * NRIM + n) * 768 + 256 + r];
    }
    if (t < NRIM) sm[t] = g_mask[b * NRIM + t];
    __syncthreads();

    for (int d = t; d < 144; d += 256) {
        const int h = d / 36, r = d % 36, n = r / 6, m = r % 6;
        float s = 0.f;
#pragma unroll
        for (int k = 0; k < CKS; k++)
            s += sq[n * 128 + h * CKS + k] * sk[m * 128 + h * CKS + k];
        sc[d] = s * 0.17677669529663687f;
    }
    __syncthreads();

    if (t < 24) {
        const int h = t / 6, n = t % 6;
        float mx = -1e30f;
        for (int m = 0; m < 6; m++) mx = fmaxf(mx, sc[h * 36 + n * 6 + m]);
        float e[6], sum = 0.f;
        for (int m = 0; m < 6; m++) { e[m] = expf(sc[h * 36 + n * 6 + m] - mx); sum += e[m]; }
        const float inv = sm[n] / sum;
        for (int m = 0; m < 6; m++) sp[h * 36 + n * 6 + m] = e[m] * inv;
    }
    __syncthreads();

    for (int idx = t; idx < NRIM * 400; idx += 256) {
        const int n = idx / 400, r = idx % 400, h = r / 100;
        float a = 0.f;
#pragma unroll
        for (int m = 0; m < 6; m++) a += sp[h * 36 + n * 6 + m] * sv[m * 400 + r];
        g_ctxh[((long)b * NRIM + n) * 416 + r] = __float2half(a);
    }
    if (t < 96) {
        const int n = t >> 4, r = 400 + (t & 15);
        g_ctxh[((long)b * NRIM + n) * 416 + r] = __float2half(0.f);
    }
}

// -------------------------------------------------------------------------------
extern "C" void kernel_launch(void* const* d_in, const int* in_sizes, int n_in,
                              void* d_out, int out_size)
{
    const float* x     = (const float*)d_in[0];
    const float* hs    = (const float*)d_in[1];
    const float* cs    = (const float*)d_in[2];
    const float* keyW  = (const float*)d_in[3];
    const float* keyb  = (const float*)d_in[4];
    const float* valW  = (const float*)d_in[5];
    const float* valb  = (const float*)d_in[6];
    const float* qW    = (const float*)d_in[7];
    const float* i2h   = (const float*)d_in[8];
    const float* h2h   = (const float*)d_in[9];
    const float* WkC   = (const float*)d_in[10];
    const float* WvC   = (const float*)d_in[11];
    const float* WqC   = (const float*)d_in[12];
    const float* WoC   = (const float*)d_in[13];
    float* out = (float*)d_out;

    float *kx, *q, *vx, *ckqv, *mask, *hnewf;
    uint32_t *xh, *hsh, *rnnh, *wh_val, *wh_pre, *wh_kqv, *wh_o;
    __half *hnewh, *ctxh;
    cudaGetSymbolAddress((void**)&kx,    g_kx);
    cudaGetSymbolAddress((void**)&q,     g_q);
    cudaGetSymbolAddress((void**)&vx,    g_vx);
    cudaGetSymbolAddress((void**)&ckqv,  g_ckqv);
    cudaGetSymbolAddress((void**)&mask,  g_mask);
    cudaGetSymbolAddress((void**)&hnewf, g_hnew);
    cudaGetSymbolAddress((void**)&xh,    g_xh);
    cudaGetSymbolAddress((void**)&hsh,   g_hsh);
    cudaGetSymbolAddress((void**)&rnnh,  g_rnnh);
    cudaGetSymbolAddress((void**)&hnewh, g_hnewh);
    cudaGetSymbolAddress((void**)&ctxh,  g_ctxh);
    cudaGetSymbolAddress((void**)&wh_val, g_wh_val);
    cudaGetSymbolAddress((void**)&wh_pre, g_wh_pre);
    cudaGetSymbolAddress((void**)&wh_kqv, g_wh_kqv);
    cudaGetSymbolAddress((void**)&wh_o,   g_wh_o);

    cudaFuncSetAttribute(gemm_fp16h<0>, cudaFuncAttributeMaxDynamicSharedMemorySize, GSM_PIPE);
    cudaFuncSetAttribute(gemm_fp16h<1>, cudaFuncAttributeMaxDynamicSharedMemorySize, GSM_PIPE);
    cudaFuncSetAttribute(gemm_fp16h<2>, cudaFuncAttributeMaxDynamicSharedMemorySize, GSM_PIPE);

    // ---- fork a second graph branch for the independent fp32 kx+q GEMM ----
    cudaStream_t s2;
    cudaEvent_t eF, eJ;
    cudaStreamCreateWithFlags(&s2, cudaStreamNonBlocking);
    cudaEventCreateWithFlags(&eF, cudaEventDisableTiming);
    cudaEventCreateWithFlags(&eJ, cudaEventDisableTiming);

    cudaEventRecord(eF, 0);
    cudaStreamWaitEvent(s2, eF, 0);
    // Branch B (s2): 1+3) kx + q fused fp32 launch (reads raw inputs only)
    gemm128_fat<<<dim3(1, 64, 7), 256, 0, s2>>>(x, keyW, keyb, kx, hs, qW, q);

    // Branch A (origin stream): converts + packs + vx
    const int nA = BSZ * 256, nB = BSZ * 768;
    f2h2<<<(nA + nB + 255) / 256, 256>>>((const float2*)x, xh, nA,
                                         (const float2*)hs, hsh, nB);
    pack_w<<<896, 256>>>(valW, 512, 800, 0, nullptr, 0, 0, 0,
                         wh_val, 800, 896, 512, 0);
    // 2) vx = x @ value_W + value_b  (fp16, EP=0)
    gemm_fp16h<0><<<dim3(7, 64, 1), 256, GSM_PIPE>>>(xh, 256, 256, 0, xh, 256, 0,
                                                     wh_val, 896, 0, 256, valb, vx, 800, 800, 0,
                                                     nullptr, nullptr, nullptr, nullptr, nullptr, nullptr);
    pack_pre<<<dim3(1344, 1, NRIM), 256>>>(i2h, h2h, wh_pre);
    pack_kqv<<<dim3(384, 1, NRIM), 256>>>(WkC, WqC, WvC, wh_kqv);
    pack_w<<<dim3(208, 1, NRIM), 256>>>(WoC, 400, 256, 400L * 256, nullptr, 0, 0, 0,
                                        wh_o, 256, 256, 416, 208L * 256);

    // ---- join branch B before attention (needs kx, q) ----
    cudaEventRecord(eJ, s2);
    cudaStreamWaitEvent(0, eJ, 0);

    // 4) input attention + top-k + rnn_in (half)
    attn_kernel<<<BSZ, 256>>>(keyb, valb);
    // 5+6+7) preact GEMM + fused LSTM epilogue (EP=1)
    gemm_fp16h<1><<<dim3(8, 64, NRIM), 256, GSM_PIPE>>>(rnnh, 208, NRIM * 208, 208,
                                                        hsh, 768, 128,
                                                        wh_pre, 1024, 336L * 1024, 336,
                                                        nullptr, nullptr, 1024, 0, 0,
                                                        cs, out, mask, hnewf, hnewh, nullptr);
    // 8) ck|cq|cv = h_new @ [Wk|Wq|Wv]  (fp16, EP=0)
    gemm_fp16h<0><<<dim3(6, 64, NRIM), 256, GSM_PIPE>>>((uint32_t*)hnewh, 128, NRIM * 128, 128,
                                                        (uint32_t*)hnewh, 128, 128,
                                                        wh_kqv, 768, 128L * 768, 128,
                                                        nullptr, ckqv, 768, NRIM * 768, 768,
                                                        nullptr, nullptr, nullptr, nullptr, nullptr, nullptr);
    // 9) communication attention -> ctx (half)
    cattn_kernel<<<BSZ, 256>>>();
    // 10+11) hcm GEMM + fused final-h epilogue (EP=2)
    gemm_fp16h<2><<<dim3(2, 64, NRIM), 256, GSM_PIPE>>>((uint32_t*)ctxh, 208, NRIM * 208, 208,
                                                        (uint32_t*)ctxh, 208, 208,
                                                        wh_o, 256, 208L * 256, 208,
                                                        nullptr, nullptr, 256, 0, 0,
                                                        nullptr, out, mask, hnewf, nullptr, hs);
    // NOTE: s2/eF/eJ intentionally not destroyed — destroying capture-participating
    // resources is illegal; handles are few and graph replays never re-enter here.
}